// round 14
// baseline (speedup 1.0000x reference)
#include <cuda_runtime.h>
#include <cuda_fp16.h>
#include <cstdint>

#define NN 50000
#define EE 800000
#define RR 6
#define FF 128
#define SEG (RR * NN)

// ---------------- scratch (static device globals; no allocations) ----------------
__device__ __align__(16) __half g_nodeH[(size_t)NN * FF];  // 12.8 MB fp16 node_h
__device__ __align__(16) float g_v1[RR * FF];
__device__ __align__(16) float g_v2[RR * FF];
__device__ __align__(16) __half g_Wh[RR * FF * FF];        // [r][o][f] = W[r][f][o] fp16
__device__ __align__(16) __half g_Wc1h[FF * FF];           // [o][k] fp16
__device__ __align__(16) __half g_Wc2h[FF * FF];
__device__ __align__(16) float g_d1[NN * RR];              // per-node attention dots
__device__ __align__(16) float g_d2[NN * RR];
__device__ __align__(16) float g_e1[SEG];
__device__ __align__(16) float g_e2[SEG];
__device__ __align__(16) int g_cnt[SEG];                   // zero-init; restored in gemm epilogue
__device__ __align__(16) int g_off[SEG];                   // local (per-512-block) prescan
__device__ __align__(16) int g_bsum[1024];
__device__ __align__(16) int g_src_sorted[EE];

__device__ __forceinline__ void cpa16(void* dst_smem, const void* src) {
    uint32_t d = (uint32_t)__cvta_generic_to_shared(dst_smem);
    asm volatile("cp.async.cg.shared.global [%0], [%1], 16;" :: "r"(d), "l"(src));
}

// ---------------- K0: precompute v1,v2, fp16 W^T, Wc convert (blocks >= 768) ----------------
__global__ void precompute_kernel(const float* __restrict__ W,
                                  const float* __restrict__ att1,
                                  const float* __restrict__ att2,
                                  const float* __restrict__ Wc) {
    if (blockIdx.x >= RR * FF) {
        int o = blockIdx.x - RR * FF;
        int k = threadIdx.x;
        g_Wc1h[o * FF + k] = __float2half_rn(Wc[o * 256 + k]);
        g_Wc2h[o * FF + k] = __float2half_rn(Wc[o * 256 + 128 + k]);
        return;
    }
    __shared__ float red1[128];
    __shared__ float red2[128];
    int rf = blockIdx.x;
    int r  = rf >> 7, f = rf & 127;
    int o  = threadIdx.x;
    float w = W[rf * 128 + o];
    g_Wh[(size_t)r * (FF * FF) + o * FF + f] = __float2half_rn(w);

    red1[o] = w * att1[o];
    red2[o] = w * att2[o];
    __syncthreads();
    for (int s = 64; s > 0; s >>= 1) {
        if (o < s) { red1[o] += red1[o + s]; red2[o] += red2[o + s]; }
        __syncthreads();
    }
    if (o == 0) { g_v1[rf] = red1[0]; g_v2[rf] = red2[0]; }
}

// ---------------- convert node_h -> fp16 ----------------
__global__ void nodeh_convert_kernel(const float* __restrict__ node_h) {
    size_t i = (size_t)blockIdx.x * blockDim.x + threadIdx.x;
    if (i >= (size_t)NN * FF / 8) return;
    const float4* p = reinterpret_cast<const float4*>(node_h) + i * 2;
    float4 a = p[0], b = p[1];
    __half2 h0 = __floats2half2_rn(a.x, a.y);
    __half2 h1 = __floats2half2_rn(a.z, a.w);
    __half2 h2 = __floats2half2_rn(b.x, b.y);
    __half2 h3 = __floats2half2_rn(b.z, b.w);
    uint4 o;
    o.x = *reinterpret_cast<uint32_t*>(&h0);
    o.y = *reinterpret_cast<uint32_t*>(&h1);
    o.z = *reinterpret_cast<uint32_t*>(&h2);
    o.w = *reinterpret_cast<uint32_t*>(&h3);
    reinterpret_cast<uint4*>(g_nodeH)[i] = o;
}

// ---------------- dots: d_h[n,r] = dot(h16_n, v_h[r])  (one warp per node) ----------------
__global__ __launch_bounds__(256) void dots_kernel() {
    __shared__ float v1s[RR * FF];
    __shared__ float v2s[RR * FF];
    int t = threadIdx.x;
#pragma unroll
    for (int j = 0; j < 3; j++) { v1s[t + 256 * j] = g_v1[t + 256 * j]; v2s[t + 256 * j] = g_v2[t + 256 * j]; }
    __syncthreads();
    int n = blockIdx.x * 8 + (t >> 5);
    if (n >= NN) return;
    int l = t & 31;
    uint2 u = reinterpret_cast<const uint2*>(g_nodeH)[(size_t)n * 32 + l];
    float2 x01 = __half22float2(*reinterpret_cast<__half2*>(&u.x));
    float2 x23 = __half22float2(*reinterpret_cast<__half2*>(&u.y));
#pragma unroll
    for (int r = 0; r < RR; r++) {
        const float* w1 = v1s + r * FF + l * 4;
        const float* w2 = v2s + r * FF + l * 4;
        float p1 = x01.x * w1[0] + x01.y * w1[1] + x23.x * w1[2] + x23.y * w1[3];
        float p2 = x01.x * w2[0] + x01.y * w2[1] + x23.x * w2[2] + x23.y * w2[3];
#pragma unroll
        for (int s = 16; s > 0; s >>= 1) {
            p1 += __shfl_xor_sync(0xffffffffu, p1, s);
            p2 += __shfl_xor_sync(0xffffffffu, p2, s);
        }
        if (l == 0) { g_d1[n * RR + r] = p1; g_d2[n * RR + r] = p2; }
    }
}

// ---------------- CSR build ----------------
__global__ void hist_kernel(const int4* __restrict__ edst4, const int4* __restrict__ erel4) {
    int i = blockIdx.x * blockDim.x + threadIdx.x;
    if (i >= EE / 8) return;
    int4 d0 = edst4[i * 2], d1 = edst4[i * 2 + 1];
    int4 r0 = erel4[i * 2], r1 = erel4[i * 2 + 1];
    atomicAdd(&g_cnt[r0.x * NN + d0.x], 1);
    atomicAdd(&g_cnt[r0.y * NN + d0.y], 1);
    atomicAdd(&g_cnt[r0.z * NN + d0.z], 1);
    atomicAdd(&g_cnt[r0.w * NN + d0.w], 1);
    atomicAdd(&g_cnt[r1.x * NN + d1.x], 1);
    atomicAdd(&g_cnt[r1.y * NN + d1.y], 1);
    atomicAdd(&g_cnt[r1.z * NN + d1.z], 1);
    atomicAdd(&g_cnt[r1.w * NN + d1.w], 1);
}

__global__ void scan1_kernel() {
    __shared__ int wsum[16];
    int tid = threadIdx.x;
    int idx = blockIdx.x * 512 + tid;
    int lane = tid & 31, wid = tid >> 5;
    int v = (idx < SEG) ? g_cnt[idx] : 0;
    int incl = v;
#pragma unroll
    for (int s = 1; s < 32; s <<= 1) {
        int u = __shfl_up_sync(0xffffffffu, incl, s);
        if (lane >= s) incl += u;
    }
    if (lane == 31) wsum[wid] = incl;
    __syncthreads();
    if (wid == 0) {
        int wv = (lane < 16) ? wsum[lane] : 0;
        int wi = wv;
#pragma unroll
        for (int s = 1; s < 16; s <<= 1) {
            int u = __shfl_up_sync(0xffffffffu, wi, s);
            if (lane >= s) wi += u;
        }
        if (lane < 16) wsum[lane] = wi - wv;
        if (lane == 15) g_bsum[blockIdx.x] = wi;
    }
    __syncthreads();
    if (idx < SEG) g_off[idx] = incl - v + wsum[wid];
}

__global__ void scan2_kernel(int nblk) {
    __shared__ int wsum[32];
    int tid = threadIdx.x;
    int lane = tid & 31, wid = tid >> 5;
    int v = (tid < nblk) ? g_bsum[tid] : 0;
    int incl = v;
#pragma unroll
    for (int s = 1; s < 32; s <<= 1) {
        int u = __shfl_up_sync(0xffffffffu, incl, s);
        if (lane >= s) incl += u;
    }
    if (lane == 31) wsum[wid] = incl;
    __syncthreads();
    if (wid == 0) {
        int wv = wsum[lane];
        int wi = wv;
#pragma unroll
        for (int s = 1; s < 32; s <<= 1) {
            int u = __shfl_up_sync(0xffffffffu, wi, s);
            if (lane >= s) wi += u;
        }
        wsum[lane] = wi - wv;
    }
    __syncthreads();
    if (tid < nblk) g_bsum[tid] = incl - v + wsum[wid];
}

__global__ void permute_kernel(const int4* __restrict__ esrc4,
                               const int4* __restrict__ edst4,
                               const int4* __restrict__ erel4) {
    int i = blockIdx.x * blockDim.x + threadIdx.x;
    if (i >= EE / 4) return;
    int4 s = esrc4[i];
    int4 d = edst4[i];
    int4 r = erel4[i];
    int k0 = r.x * NN + d.x;
    int k1 = r.y * NN + d.y;
    int k2 = r.z * NN + d.z;
    int k3 = r.w * NN + d.w;
    int p0 = atomicAdd(&g_off[k0], 1) + g_bsum[k0 >> 9];
    int p1 = atomicAdd(&g_off[k1], 1) + g_bsum[k1 >> 9];
    int p2 = atomicAdd(&g_off[k2], 1) + g_bsum[k2 >> 9];
    int p3 = atomicAdd(&g_off[k3], 1) + g_bsum[k3 >> 9];
    asm volatile("st.global.cs.u32 [%0], %1;" :: "l"(g_src_sorted + p0), "r"(s.x) : "memory");
    asm volatile("st.global.cs.u32 [%0], %1;" :: "l"(g_src_sorted + p1), "r"(s.y) : "memory");
    asm volatile("st.global.cs.u32 [%0], %1;" :: "l"(g_src_sorted + p2), "r"(s.z) : "memory");
    asm volatile("st.global.cs.u32 [%0], %1;" :: "l"(g_src_sorted + p3), "r"(s.w) : "memory");
}

// ---------------- escan: e_h[seg] = sum over segment edges of d_h[src,r] ----------------
__global__ void escan_kernel() {
    int seg = blockIdx.x * blockDim.x + threadIdx.x;
    if (seg >= SEG) return;
    int r = seg / NN;
    int deg = g_cnt[seg];
    int off = g_off[seg] + g_bsum[seg >> 9] - deg;
    float e1 = 0.f, e2 = 0.f;
    int e = 0;
    for (; e + 2 <= deg; e += 2) {
        int s0 = g_src_sorted[off + e];
        int s1 = g_src_sorted[off + e + 1];
        e1 += g_d1[s0 * RR + r] + g_d1[s1 * RR + r];
        e2 += g_d2[s0 * RR + r] + g_d2[s1 * RR + r];
    }
    if (e < deg) {
        int s0 = g_src_sorted[off + e];
        e1 += g_d1[s0 * RR + r];
        e2 += g_d2[s0 * RR + r];
    }
    g_e1[seg] = e1;
    g_e2[seg] = e2;
}

// ---------------- K4: fused gather + softmax + factored GEMM (2 blocks/SM) ----------------
__device__ __forceinline__ void mma16(float d[4], uint32_t a0, uint32_t a1, uint32_t a2, uint32_t a3,
                                      uint32_t b0, uint32_t b1) {
    asm volatile(
        "mma.sync.aligned.m16n8k16.row.col.f32.f16.f16.f32 "
        "{%0,%1,%2,%3},{%4,%5,%6,%7},{%8,%9},{%0,%1,%2,%3};"
        : "+f"(d[0]), "+f"(d[1]), "+f"(d[2]), "+f"(d[3])
        : "r"(a0), "r"(a1), "r"(a2), "r"(a3), "r"(b0), "r"(b1));
}

#define STR 136
#define AH_OFF 0                         // [2][64][STR]; Y/Z alias after stage 1
#define BW_OFF (2 * 64 * STR)            // [128][STR] single-buffered W
#define WC2_OFF (BW_OFF + 128 * STR)     // [128][STR]
#define CS_OFF (WC2_OFF + 128 * STR)     // float c1s[384], c2s[384]
#define GEMM_SMEM (CS_OFF * 2 + 768 * 4) // 107520 bytes

__global__ __launch_bounds__(256, 2) void gemm_kernel(float* __restrict__ out,
                                                      const float* __restrict__ bc) {
    extern __shared__ __half sh[];
    __half* Ah   = sh + AH_OFF;
    __half* Bw   = sh + BW_OFF;
    __half* Wc2s = sh + WC2_OFF;
    float* c1s = reinterpret_cast<float*>(sh + CS_OFF);
    float* c2s = c1s + 384;

    int n0 = blockIdx.x * 64;
    int t = threadIdx.x;
    int warp = t >> 5, lane = t & 31;
    int wm = warp >> 2, wn = warp & 3;
    int g = lane >> 2, tg = lane & 3;
    int rowa = wm * 32 + g;

    auto ldW = [&](__half* dst, const __half* src) {
#pragma unroll
        for (int j = 0; j < 8; j++) {
            int lin = t + 256 * j;
            int o = lin >> 4;
            int c8 = (lin & 15) * 8;
            cpa16(dst + o * STR + c8, src + o * FF + c8);
        }
    };

    // gather A tile for relation s into buf: warp w handles rows {w, w+8, ..., w+56}
    auto gatherA = [&](int s, int buf) {
        const uint2* h2 = reinterpret_cast<const uint2*>(g_nodeH);
        __half* base = Ah + buf * 64 * STR;
#pragma unroll 1
        for (int k = 0; k < 8; k++) {
            int row = warp + k * 8;
            int n = n0 + row;
            float4 acc = make_float4(0.f, 0.f, 0.f, 0.f);
            if (n < NN) {
                int seg = s * NN + n;
                int deg = g_cnt[seg];
                int off = g_off[seg] + g_bsum[seg >> 9] - deg;
                int e = 0;
                for (; e + 2 <= deg; e += 2) {
                    int i0 = g_src_sorted[off + e];
                    int i1 = g_src_sorted[off + e + 1];
                    uint2 u0 = h2[(size_t)i0 * 32 + lane];
                    uint2 u1 = h2[(size_t)i1 * 32 + lane];
                    float2 a0 = __half22float2(*reinterpret_cast<__half2*>(&u0.x));
                    float2 a1 = __half22float2(*reinterpret_cast<__half2*>(&u0.y));
                    float2 b0 = __half22float2(*reinterpret_cast<__half2*>(&u1.x));
                    float2 b1 = __half22float2(*reinterpret_cast<__half2*>(&u1.y));
                    acc.x += a0.x + b0.x; acc.y += a0.y + b0.y;
                    acc.z += a1.x + b1.x; acc.w += a1.y + b1.y;
                }
                if (e < deg) {
                    int i0 = g_src_sorted[off + e];
                    uint2 u0 = h2[(size_t)i0 * 32 + lane];
                    float2 a0 = __half22float2(*reinterpret_cast<__half2*>(&u0.x));
                    float2 a1 = __half22float2(*reinterpret_cast<__half2*>(&u0.y));
                    acc.x += a0.x; acc.y += a0.y; acc.z += a1.x; acc.w += a1.y;
                }
            }
            __half2 h01 = __floats2half2_rn(acc.x, acc.y);
            __half2 h23 = __floats2half2_rn(acc.z, acc.w);
            uint2 pk;
            pk.x = *reinterpret_cast<uint32_t*>(&h01);
            pk.y = *reinterpret_cast<uint32_t*>(&h23);
            *reinterpret_cast<uint2*>(base + row * STR + lane * 4) = pk;
        }
    };

    // prologue: W0 via cp.async; gather A0/A1 directly
    ldW(Bw, g_Wh);
    asm volatile("cp.async.commit_group;" ::: "memory");
    gatherA(0, 0);
    gatherA(1, 1);

    // fused softmax (threads 0..63; one node each); g_cnt read here, zeroed in epilogue
    if (t < 64) {
        int n = n0 + t;
        if (n < NN) {
            float e1[RR], e2[RR], dg[RR];
#pragma unroll
            for (int r = 0; r < RR; r++) {
                dg[r] = 1.0f + (float)g_cnt[r * NN + n];
                e1[r] = g_e1[r * NN + n] / dg[r];
                e2[r] = g_e2[r * NN + n] / dg[r];
            }
            float m1 = e1[0], m2 = e2[0];
#pragma unroll
            for (int r = 1; r < RR; r++) { m1 = fmaxf(m1, e1[r]); m2 = fmaxf(m2, e2[r]); }
            float s1 = 0.f, s2 = 0.f;
#pragma unroll
            for (int r = 0; r < RR; r++) {
                e1[r] = __expf(e1[r] - m1); s1 += e1[r];
                e2[r] = __expf(e2[r] - m2); s2 += e2[r];
            }
            float i1 = 1.0f / s1, i2 = 1.0f / s2;
#pragma unroll
            for (int r = 0; r < RR; r++) {
                c1s[t * 6 + r] = e1[r] * i1 / dg[r];
                c2s[t * 6 + r] = e2[r] * i2 / dg[r];
            }
        } else {
#pragma unroll
            for (int r = 0; r < RR; r++) { c1s[t * 6 + r] = 0.f; c2s[t * 6 + r] = 0.f; }
        }
    }
    asm volatile("cp.async.wait_group 0;" ::: "memory");
    __syncthreads();

    float P[2][4][4], Y[2][4][4], Z[2][4][4];
#pragma unroll
    for (int mi = 0; mi < 2; mi++)
#pragma unroll
        for (int ni = 0; ni < 4; ni++)
#pragma unroll
            for (int j = 0; j < 4; j++) { P[mi][ni][j] = 0.f; Y[mi][ni][j] = 0.f; Z[mi][ni][j] = 0.f; }

    auto mmastep = [&](const __half* Abase, const __half* Bbase) {
#pragma unroll
        for (int ks = 0; ks < 8; ks++) {
            int k0 = ks * 16;
            uint32_t a[2][4];
#pragma unroll
            for (int mi = 0; mi < 2; mi++) {
                const __half* ap = Abase + (rowa + mi * 16) * STR + k0 + tg * 2;
                a[mi][0] = *reinterpret_cast<const uint32_t*>(ap);
                a[mi][1] = *reinterpret_cast<const uint32_t*>(ap + 8 * STR);
                a[mi][2] = *reinterpret_cast<const uint32_t*>(ap + 8);
                a[mi][3] = *reinterpret_cast<const uint32_t*>(ap + 8 * STR + 8);
            }
            uint32_t b[4][2];
#pragma unroll
            for (int ni = 0; ni < 4; ni++) {
                const __half* bp = Bbase + (wn * 32 + ni * 8 + g) * STR + k0 + tg * 2;
                b[ni][0] = *reinterpret_cast<const uint32_t*>(bp);
                b[ni][1] = *reinterpret_cast<const uint32_t*>(bp + 8);
            }
#pragma unroll
            for (int mi = 0; mi < 2; mi++)
#pragma unroll
                for (int ni = 0; ni < 4; ni++)
                    mma16(P[mi][ni], a[mi][0], a[mi][1], a[mi][2], a[mi][3],
                          b[ni][0], b[ni][1]);
        }
    };

    for (int s = 0; s < 6; s++) {
        mmastep(Ah + (s & 1) * 64 * STR, Bw);
        __syncthreads();   // all warps done reading Bw and Ah[s&1]
        if (s < 5) {
            ldW(Bw, g_Wh + (size_t)(s + 1) * (FF * FF));
            asm volatile("cp.async.commit_group;" ::: "memory");
            if (s + 2 < 6) gatherA(s + 2, s & 1);   // write into just-freed buffer
        }
        // fold P into Y, Z
#pragma unroll
        for (int mi = 0; mi < 2; mi++) {
            int rl = rowa + mi * 16;
            float c1a = c1s[rl * 6 + s];
            float c1b = c1s[(rl + 8) * 6 + s];
            float c2a = c2s[rl * 6 + s];
            float c2b = c2s[(rl + 8) * 6 + s];
#pragma unroll
            for (int ni = 0; ni < 4; ni++) {
                Y[mi][ni][0] += c1a * P[mi][ni][0];
                Y[mi][ni][1] += c1a * P[mi][ni][1];
                Y[mi][ni][2] += c1b * P[mi][ni][2];
                Y[mi][ni][3] += c1b * P[mi][ni][3];
                Z[mi][ni][0] += c2a * P[mi][ni][0];
                Z[mi][ni][1] += c2a * P[mi][ni][1];
                Z[mi][ni][2] += c2b * P[mi][ni][2];
                Z[mi][ni][3] += c2b * P[mi][ni][3];
                P[mi][ni][0] = 0.f; P[mi][ni][1] = 0.f;
                P[mi][ni][2] = 0.f; P[mi][ni][3] = 0.f;
            }
        }
        if (s < 5) {
            asm volatile("cp.async.wait_group 0;" ::: "memory");
            __syncthreads();   // W(s+1) + gathered A visible before next mma
        }
    }

    __syncthreads();
    ldW(Bw, g_Wc1h);
    ldW(Wc2s, g_Wc2h);
    asm volatile("cp.async.commit_group;" ::: "memory");

    // stage Y,Z (fp16) into the dead A region
    __half* Yt = Ah;
    __half* Zt = Ah + 64 * STR;
#pragma unroll
    for (int mi = 0; mi < 2; mi++) {
        int row = rowa + mi * 16;
#pragma unroll
        for (int ni = 0; ni < 4; ni++) {
            int col = wn * 32 + ni * 8 + tg * 2;
            *reinterpret_cast<__half2*>(Yt + row * STR + col) =
                __floats2half2_rn(Y[mi][ni][0], Y[mi][ni][1]);
            *reinterpret_cast<__half2*>(Yt + (row + 8) * STR + col) =
                __floats2half2_rn(Y[mi][ni][2], Y[mi][ni][3]);
            *reinterpret_cast<__half2*>(Zt + row * STR + col) =
                __floats2half2_rn(Z[mi][ni][0], Z[mi][ni][1]);
            *reinterpret_cast<__half2*>(Zt + (row + 8) * STR + col) =
                __floats2half2_rn(Z[mi][ni][2], Z[mi][ni][3]);
        }
    }
    asm volatile("cp.async.wait_group 0;" ::: "memory");
    __syncthreads();

    // stage 2: out = Y@Wc1^T + Z@Wc2^T
    mmastep(Yt, Bw);
    mmastep(Zt, Wc2s);

    // restore g_cnt = 0 (after all gather/softmax reads)
    if (t < 64) {
        int n = n0 + t;
        if (n < NN) {
#pragma unroll
            for (int r = 0; r < RR; r++) g_cnt[r * NN + n] = 0;
        }
    }

#pragma unroll
    for (int mi = 0; mi < 2; mi++) {
        int ra = n0 + rowa + mi * 16;
#pragma unroll
        for (int ni = 0; ni < 4; ni++) {
            int col = wn * 32 + ni * 8 + tg * 2;
            float b0 = 6.0f * bc[col];
            float b1 = 6.0f * bc[col + 1];
            if (ra < NN) {
                float2 v = make_float2(P[mi][ni][0] + b0, P[mi][ni][1] + b1);
                *reinterpret_cast<float2*>(&out[(size_t)ra * FF + col]) = v;
            }
            if (ra + 8 < NN) {
                float2 v = make_float2(P[mi][ni][2] + b0, P[mi][ni][3] + b1);
                *reinterpret_cast<float2*>(&out[(size_t)(ra + 8) * FF + col]) = v;
            }
        }
    }
}

// ---------------- launch ----------------
extern "C" void kernel_launch(void* const* d_in, const int* in_sizes, int n_in,
                              void* d_out, int out_size) {
    const float* node_h = (const float*)d_in[0];
    const float* W      = (const float*)d_in[1];
    const float* att1   = (const float*)d_in[2];
    const float* att2   = (const float*)d_in[3];
    const float* Wc     = (const float*)d_in[4];
    const float* bc     = (const float*)d_in[5];
    const int*   esrc   = (const int*)d_in[6];
    const int*   edst   = (const int*)d_in[7];
    const int*   erel   = (const int*)d_in[8];
    float* out = (float*)d_out;

    static int inited = 0;
    static cudaStream_t s1;
    static cudaEvent_t evFork, evPre;
    if (!inited) {
        cudaFuncSetAttribute(gemm_kernel, cudaFuncAttributeMaxDynamicSharedMemorySize, GEMM_SMEM);
        cudaStreamCreateWithFlags(&s1, cudaStreamNonBlocking);
        cudaEventCreateWithFlags(&evFork, cudaEventDisableTiming);
        cudaEventCreateWithFlags(&evPre, cudaEventDisableTiming);
        inited = 1;
    }

    const int nblk1 = (SEG + 511) / 512;

    // fork: precompute branch on s1 (independent of CSR build)
    cudaEventRecord(evFork, 0);
    cudaStreamWaitEvent(s1, evFork, 0);
    if (out_size >= NN * FF + RR * FF * FF) {
        cudaMemcpyAsync(out + (size_t)NN * FF, W,
                        sizeof(float) * RR * FF * FF, cudaMemcpyDeviceToDevice, s1);
    }
    precompute_kernel<<<RR * FF + FF, 128, 0, s1>>>(W, att1, att2, Wc);
    nodeh_convert_kernel<<<(NN * FF / 8 + 255) / 256, 256, 0, s1>>>(node_h);
    dots_kernel<<<(NN + 7) / 8, 256, 0, s1>>>();
    cudaEventRecord(evPre, s1);

    // CSR branch on stream 0 (g_cnt all-zero by invariant)
    hist_kernel<<<(EE / 8 + 255) / 256, 256>>>((const int4*)edst, (const int4*)erel);
    scan1_kernel<<<nblk1, 512>>>();
    scan2_kernel<<<1, 1024>>>(nblk1);
    permute_kernel<<<(EE / 4 + 255) / 256, 256>>>((const int4*)esrc, (const int4*)edst,
                                                  (const int4*)erel);

    // join precompute (dots) before escan
    cudaStreamWaitEvent(0, evPre, 0);
    escan_kernel<<<(SEG + 255) / 256, 256>>>();
    gemm_kernel<<<(NN + 63) / 64, 256, GEMM_SMEM>>>(out, bc);
}

// round 15
// speedup vs baseline: 1.1592x; 1.1592x over previous
#include <cuda_runtime.h>
#include <cuda_fp16.h>
#include <cstdint>

#define NN 50000
#define EE 800000
#define RR 6
#define FF 128
#define SEG (RR * NN)

// ---------------- scratch (static device globals; no allocations) ----------------
__device__ __align__(16) __half g_nodeH[(size_t)NN * FF];  // 12.8 MB fp16 node_h
__device__ __align__(16) __half g_aggH[(size_t)SEG * FF];  // 76.8 MB fp16 agg
__device__ __align__(16) float g_v1[RR * FF];
__device__ __align__(16) float g_v2[RR * FF];
__device__ __align__(16) __half g_Wh[RR * FF * FF];        // [r][o][f] = W[r][f][o] fp16
__device__ __align__(16) __half g_Wc1h[FF * FF];           // [o][k] fp16
__device__ __align__(16) __half g_Wc2h[FF * FF];
__device__ __align__(16) float g_e1[SEG];
__device__ __align__(16) float g_e2[SEG];
__device__ __align__(16) int g_cnt[SEG];                   // zero-init; restored in gemm
__device__ __align__(16) int g_off[SEG];                   // local (per-512-block) prescan
__device__ __align__(16) int g_bsum[1024];
__device__ __align__(16) int g_src_sorted[EE];

__device__ __forceinline__ void cpa16(void* dst_smem, const void* src) {
    uint32_t d = (uint32_t)__cvta_generic_to_shared(dst_smem);
    asm volatile("cp.async.cg.shared.global [%0], [%1], 16;" :: "r"(d), "l"(src));
}

// ---------------- K0: precompute v1,v2, fp16 W^T, Wc convert (blocks >= 768) ----------------
__global__ void precompute_kernel(const float* __restrict__ W,
                                  const float* __restrict__ att1,
                                  const float* __restrict__ att2,
                                  const float* __restrict__ Wc) {
    if (blockIdx.x >= RR * FF) {
        int o = blockIdx.x - RR * FF;
        int k = threadIdx.x;
        g_Wc1h[o * FF + k] = __float2half_rn(Wc[o * 256 + k]);
        g_Wc2h[o * FF + k] = __float2half_rn(Wc[o * 256 + 128 + k]);
        return;
    }
    __shared__ float red1[128];
    __shared__ float red2[128];
    int rf = blockIdx.x;
    int r  = rf >> 7, f = rf & 127;
    int o  = threadIdx.x;
    float w = W[rf * 128 + o];
    g_Wh[(size_t)r * (FF * FF) + o * FF + f] = __float2half_rn(w);

    red1[o] = w * att1[o];
    red2[o] = w * att2[o];
    __syncthreads();
    for (int s = 64; s > 0; s >>= 1) {
        if (o < s) { red1[o] += red1[o + s]; red2[o] += red2[o + s]; }
        __syncthreads();
    }
    if (o == 0) { g_v1[rf] = red1[0]; g_v2[rf] = red2[0]; }
}

// ---------------- convert node_h -> fp16 ----------------
__global__ void nodeh_convert_kernel(const float* __restrict__ node_h) {
    size_t i = (size_t)blockIdx.x * blockDim.x + threadIdx.x;
    if (i >= (size_t)NN * FF / 8) return;
    const float4* p = reinterpret_cast<const float4*>(node_h) + i * 2;
    float4 a = p[0], b = p[1];
    __half2 h0 = __floats2half2_rn(a.x, a.y);
    __half2 h1 = __floats2half2_rn(a.z, a.w);
    __half2 h2 = __floats2half2_rn(b.x, b.y);
    __half2 h3 = __floats2half2_rn(b.z, b.w);
    uint4 o;
    o.x = *reinterpret_cast<uint32_t*>(&h0);
    o.y = *reinterpret_cast<uint32_t*>(&h1);
    o.z = *reinterpret_cast<uint32_t*>(&h2);
    o.w = *reinterpret_cast<uint32_t*>(&h3);
    reinterpret_cast<uint4*>(g_nodeH)[i] = o;
}

// ---------------- CSR build ----------------
__global__ void hist_kernel(const int4* __restrict__ edst4, const int4* __restrict__ erel4) {
    int i = blockIdx.x * blockDim.x + threadIdx.x;
    if (i >= EE / 8) return;
    int4 d0 = edst4[i * 2], d1 = edst4[i * 2 + 1];
    int4 r0 = erel4[i * 2], r1 = erel4[i * 2 + 1];
    atomicAdd(&g_cnt[r0.x * NN + d0.x], 1);
    atomicAdd(&g_cnt[r0.y * NN + d0.y], 1);
    atomicAdd(&g_cnt[r0.z * NN + d0.z], 1);
    atomicAdd(&g_cnt[r0.w * NN + d0.w], 1);
    atomicAdd(&g_cnt[r1.x * NN + d1.x], 1);
    atomicAdd(&g_cnt[r1.y * NN + d1.y], 1);
    atomicAdd(&g_cnt[r1.z * NN + d1.z], 1);
    atomicAdd(&g_cnt[r1.w * NN + d1.w], 1);
}

__global__ void scan1_kernel() {
    __shared__ int wsum[16];
    int tid = threadIdx.x;
    int idx = blockIdx.x * 512 + tid;
    int lane = tid & 31, wid = tid >> 5;
    int v = (idx < SEG) ? g_cnt[idx] : 0;
    int incl = v;
#pragma unroll
    for (int s = 1; s < 32; s <<= 1) {
        int u = __shfl_up_sync(0xffffffffu, incl, s);
        if (lane >= s) incl += u;
    }
    if (lane == 31) wsum[wid] = incl;
    __syncthreads();
    if (wid == 0) {
        int wv = (lane < 16) ? wsum[lane] : 0;
        int wi = wv;
#pragma unroll
        for (int s = 1; s < 16; s <<= 1) {
            int u = __shfl_up_sync(0xffffffffu, wi, s);
            if (lane >= s) wi += u;
        }
        if (lane < 16) wsum[lane] = wi - wv;
        if (lane == 15) g_bsum[blockIdx.x] = wi;
    }
    __syncthreads();
    if (idx < SEG) g_off[idx] = incl - v + wsum[wid];
}

__global__ void scan2_kernel(int nblk) {
    __shared__ int wsum[32];
    int tid = threadIdx.x;
    int lane = tid & 31, wid = tid >> 5;
    int v = (tid < nblk) ? g_bsum[tid] : 0;
    int incl = v;
#pragma unroll
    for (int s = 1; s < 32; s <<= 1) {
        int u = __shfl_up_sync(0xffffffffu, incl, s);
        if (lane >= s) incl += u;
    }
    if (lane == 31) wsum[wid] = incl;
    __syncthreads();
    if (wid == 0) {
        int wv = wsum[lane];
        int wi = wv;
#pragma unroll
        for (int s = 1; s < 32; s <<= 1) {
            int u = __shfl_up_sync(0xffffffffu, wi, s);
            if (lane >= s) wi += u;
        }
        wsum[lane] = wi - wv;
    }
    __syncthreads();
    if (tid < nblk) g_bsum[tid] = incl - v + wsum[wid];
}

__global__ void permute_kernel(const int4* __restrict__ esrc4,
                               const int4* __restrict__ edst4,
                               const int4* __restrict__ erel4) {
    int i = blockIdx.x * blockDim.x + threadIdx.x;
    if (i >= EE / 4) return;
    int4 s = esrc4[i];
    int4 d = edst4[i];
    int4 r = erel4[i];
    int k0 = r.x * NN + d.x;
    int k1 = r.y * NN + d.y;
    int k2 = r.z * NN + d.z;
    int k3 = r.w * NN + d.w;
    int p0 = atomicAdd(&g_off[k0], 1) + g_bsum[k0 >> 9];
    int p1 = atomicAdd(&g_off[k1], 1) + g_bsum[k1 >> 9];
    int p2 = atomicAdd(&g_off[k2], 1) + g_bsum[k2 >> 9];
    int p3 = atomicAdd(&g_off[k3], 1) + g_bsum[k3 >> 9];
    asm volatile("st.global.cs.u32 [%0], %1;" :: "l"(g_src_sorted + p0), "r"(s.x) : "memory");
    asm volatile("st.global.cs.u32 [%0], %1;" :: "l"(g_src_sorted + p1), "r"(s.y) : "memory");
    asm volatile("st.global.cs.u32 [%0], %1;" :: "l"(g_src_sorted + p2), "r"(s.z) : "memory");
    asm volatile("st.global.cs.u32 [%0], %1;" :: "l"(g_src_sorted + p3), "r"(s.w) : "memory");
}

// ---------------- gather: one warp per (rel,dst) segment; fp16 in, fp16 out ----------------
__global__ __launch_bounds__(256) void gather_kernel() {
    int seg = blockIdx.x * 8 + (threadIdx.x >> 5);
    if (seg >= SEG) return;
    int l = threadIdx.x & 31;
    int r = seg / NN;
    int deg = g_cnt[seg];
    int off = g_off[seg] + g_bsum[seg >> 9] - deg;   // post-permute base

    const uint2* h2 = reinterpret_cast<const uint2*>(g_nodeH);
    float4 acc = make_float4(0.f, 0.f, 0.f, 0.f);
    int e = 0;
    for (; e + 4 <= deg; e += 4) {
        int i0 = g_src_sorted[off + e];
        int i1 = g_src_sorted[off + e + 1];
        int i2 = g_src_sorted[off + e + 2];
        int i3 = g_src_sorted[off + e + 3];
        uint2 u0 = h2[(size_t)i0 * 32 + l];
        uint2 u1 = h2[(size_t)i1 * 32 + l];
        uint2 u2 = h2[(size_t)i2 * 32 + l];
        uint2 u3 = h2[(size_t)i3 * 32 + l];
        float2 a0 = __half22float2(*reinterpret_cast<__half2*>(&u0.x));
        float2 a1 = __half22float2(*reinterpret_cast<__half2*>(&u0.y));
        float2 b0 = __half22float2(*reinterpret_cast<__half2*>(&u1.x));
        float2 b1 = __half22float2(*reinterpret_cast<__half2*>(&u1.y));
        float2 c0 = __half22float2(*reinterpret_cast<__half2*>(&u2.x));
        float2 c1 = __half22float2(*reinterpret_cast<__half2*>(&u2.y));
        float2 d0 = __half22float2(*reinterpret_cast<__half2*>(&u3.x));
        float2 d1 = __half22float2(*reinterpret_cast<__half2*>(&u3.y));
        acc.x += (a0.x + b0.x) + (c0.x + d0.x);
        acc.y += (a0.y + b0.y) + (c0.y + d0.y);
        acc.z += (a1.x + b1.x) + (c1.x + d1.x);
        acc.w += (a1.y + b1.y) + (c1.y + d1.y);
    }
    for (; e < deg; e++) {
        int i0 = g_src_sorted[off + e];
        uint2 ua = h2[(size_t)i0 * 32 + l];
        float2 a0 = __half22float2(*reinterpret_cast<__half2*>(&ua.x));
        float2 a1 = __half22float2(*reinterpret_cast<__half2*>(&ua.y));
        acc.x += a0.x; acc.y += a0.y; acc.z += a1.x; acc.w += a1.y;
    }

    __half2 h01 = __floats2half2_rn(acc.x, acc.y);
    __half2 h23 = __floats2half2_rn(acc.z, acc.w);
    uint32_t px = *reinterpret_cast<uint32_t*>(&h01);
    uint32_t py = *reinterpret_cast<uint32_t*>(&h23);
    asm volatile("st.global.cs.v2.u32 [%0], {%1,%2};"
                 :: "l"(reinterpret_cast<uint2*>(g_aggH) + (size_t)seg * 32 + l),
                    "r"(px), "r"(py) : "memory");

    float4 w1 = reinterpret_cast<const float4*>(g_v1)[r * 32 + l];
    float4 w2 = reinterpret_cast<const float4*>(g_v2)[r * 32 + l];
    float p1 = acc.x * w1.x + acc.y * w1.y + acc.z * w1.z + acc.w * w1.w;
    float p2 = acc.x * w2.x + acc.y * w2.y + acc.z * w2.z + acc.w * w2.w;
#pragma unroll
    for (int s = 16; s > 0; s >>= 1) {
        p1 += __shfl_xor_sync(0xffffffffu, p1, s);
        p2 += __shfl_xor_sync(0xffffffffu, p2, s);
    }
    if (l == 0) { g_e1[seg] = p1; g_e2[seg] = p2; }
}

// ---------------- K4: fused softmax + factored GEMM (3 blocks/SM) ----------------
__device__ __forceinline__ void mma16(float d[4], uint32_t a0, uint32_t a1, uint32_t a2, uint32_t a3,
                                      uint32_t b0, uint32_t b1) {
    asm volatile(
        "mma.sync.aligned.m16n8k16.row.col.f32.f16.f16.f32 "
        "{%0,%1,%2,%3},{%4,%5,%6,%7},{%8,%9},{%0,%1,%2,%3};"
        : "+f"(d[0]), "+f"(d[1]), "+f"(d[2]), "+f"(d[3])
        : "r"(a0), "r"(a1), "r"(a2), "r"(a3), "r"(b0), "r"(b1));
}

#define STR 136
#define AH_OFF 0                         // [2][64][STR]; Y/Z alias after stage 1
#define BW_OFF (2 * 64 * STR)            // [128][STR] single W buffer (Wc1 then Wc2 in stage 2)
#define CS_OFF (BW_OFF + 128 * STR)      // float c1s[384], c2s[384]
#define GEMM_SMEM (CS_OFF * 2 + 768 * 4) // 72704 bytes -> 3 blocks/SM

__global__ __launch_bounds__(256, 3) void gemm_kernel(float* __restrict__ out,
                                                      const float* __restrict__ bc) {
    extern __shared__ __half sh[];
    __half* Ah = sh + AH_OFF;
    __half* Bw = sh + BW_OFF;
    float* c1s = reinterpret_cast<float*>(sh + CS_OFF);
    float* c2s = c1s + 384;

    int n0 = blockIdx.x * 64;
    int t = threadIdx.x;
    int warp = t >> 5, lane = t & 31;
    int wm = warp >> 2, wn = warp & 3;
    int g = lane >> 2, tg = lane & 3;
    int rowa = wm * 32 + g;

    auto ldA = [&](int s, int buf) {
#pragma unroll
        for (int j = 0; j < 4; j++) {
            int lin = t + 256 * j;
            int row = lin >> 4;
            int c8 = (lin & 15) * 8;
            int n = n0 + row;
            if (n >= NN) n = 0;
            cpa16(Ah + buf * 64 * STR + row * STR + c8,
                  g_aggH + ((size_t)s * NN + n) * FF + c8);
        }
    };
    auto ldW = [&](__half* dst, const __half* src) {
#pragma unroll
        for (int j = 0; j < 8; j++) {
            int lin = t + 256 * j;
            int o = lin >> 4;
            int c8 = (lin & 15) * 8;
            cpa16(dst + o * STR + c8, src + o * FF + c8);
        }
    };

    // prologue: G0 = {A0, W0}, G1 = {A1}
    ldA(0, 0); ldW(Bw, g_Wh);
    asm volatile("cp.async.commit_group;" ::: "memory");
    ldA(1, 1);
    asm volatile("cp.async.commit_group;" ::: "memory");

    // fused softmax: threads 0..63; zero g_cnt after reading (restores invariant)
    if (t < 64) {
        int n = n0 + t;
        if (n < NN) {
            float e1[RR], e2[RR], dg[RR];
#pragma unroll
            for (int r = 0; r < RR; r++) {
                dg[r] = 1.0f + (float)g_cnt[r * NN + n];
                e1[r] = g_e1[r * NN + n] / dg[r];
                e2[r] = g_e2[r * NN + n] / dg[r];
            }
#pragma unroll
            for (int r = 0; r < RR; r++) g_cnt[r * NN + n] = 0;
            float m1 = e1[0], m2 = e2[0];
#pragma unroll
            for (int r = 1; r < RR; r++) { m1 = fmaxf(m1, e1[r]); m2 = fmaxf(m2, e2[r]); }
            float s1 = 0.f, s2 = 0.f;
#pragma unroll
            for (int r = 0; r < RR; r++) {
                e1[r] = __expf(e1[r] - m1); s1 += e1[r];
                e2[r] = __expf(e2[r] - m2); s2 += e2[r];
            }
            float i1 = 1.0f / s1, i2 = 1.0f / s2;
#pragma unroll
            for (int r = 0; r < RR; r++) {
                c1s[t * 6 + r] = e1[r] * i1 / dg[r];
                c2s[t * 6 + r] = e2[r] * i2 / dg[r];
            }
        } else {
#pragma unroll
            for (int r = 0; r < RR; r++) { c1s[t * 6 + r] = 0.f; c2s[t * 6 + r] = 0.f; }
        }
    }

    float P[2][4][4], Y[2][4][4], Z[2][4][4];
#pragma unroll
    for (int mi = 0; mi < 2; mi++)
#pragma unroll
        for (int ni = 0; ni < 4; ni++)
#pragma unroll
            for (int j = 0; j < 4; j++) { P[mi][ni][j] = 0.f; Y[mi][ni][j] = 0.f; Z[mi][ni][j] = 0.f; }

    auto mmastep = [&](const __half* Abase, const __half* Bbase) {
#pragma unroll
        for (int ks = 0; ks < 8; ks++) {
            int k0 = ks * 16;
            uint32_t a[2][4];
#pragma unroll
            for (int mi = 0; mi < 2; mi++) {
                const __half* ap = Abase + (rowa + mi * 16) * STR + k0 + tg * 2;
                a[mi][0] = *reinterpret_cast<const uint32_t*>(ap);
                a[mi][1] = *reinterpret_cast<const uint32_t*>(ap + 8 * STR);
                a[mi][2] = *reinterpret_cast<const uint32_t*>(ap + 8);
                a[mi][3] = *reinterpret_cast<const uint32_t*>(ap + 8 * STR + 8);
            }
            uint32_t b[4][2];
#pragma unroll
            for (int ni = 0; ni < 4; ni++) {
                const __half* bp = Bbase + (wn * 32 + ni * 8 + g) * STR + k0 + tg * 2;
                b[ni][0] = *reinterpret_cast<const uint32_t*>(bp);
                b[ni][1] = *reinterpret_cast<const uint32_t*>(bp + 8);
            }
#pragma unroll
            for (int mi = 0; mi < 2; mi++)
#pragma unroll
                for (int ni = 0; ni < 4; ni++)
                    mma16(P[mi][ni], a[mi][0], a[mi][1], a[mi][2], a[mi][3],
                          b[ni][0], b[ni][1]);
        }
    };

    for (int s = 0; s < 6; s++) {
        if (s == 5) { asm volatile("cp.async.wait_group 0;" ::: "memory"); }
        else        { asm volatile("cp.async.wait_group 1;" ::: "memory"); }
        __syncthreads();
        mmastep(Ah + (s & 1) * 64 * STR, Bw);
        if (s < 5) {
            __syncthreads();
            ldW(Bw, g_Wh + (size_t)(s + 1) * (FF * FF));
            asm volatile("cp.async.commit_group;" ::: "memory");
            if (s + 2 < 6) {
                ldA(s + 2, s & 1);
                asm volatile("cp.async.commit_group;" ::: "memory");
            }
        }
#pragma unroll
        for (int mi = 0; mi < 2; mi++) {
            int rl = rowa + mi * 16;
            float c1a = c1s[rl * 6 + s];
            float c1b = c1s[(rl + 8) * 6 + s];
            float c2a = c2s[rl * 6 + s];
            float c2b = c2s[(rl + 8) * 6 + s];
#pragma unroll
            for (int ni = 0; ni < 4; ni++) {
                Y[mi][ni][0] += c1a * P[mi][ni][0];
                Y[mi][ni][1] += c1a * P[mi][ni][1];
                Y[mi][ni][2] += c1b * P[mi][ni][2];
                Y[mi][ni][3] += c1b * P[mi][ni][3];
                Z[mi][ni][0] += c2a * P[mi][ni][0];
                Z[mi][ni][1] += c2a * P[mi][ni][1];
                Z[mi][ni][2] += c2b * P[mi][ni][2];
                Z[mi][ni][3] += c2b * P[mi][ni][3];
                P[mi][ni][0] = 0.f; P[mi][ni][1] = 0.f;
                P[mi][ni][2] = 0.f; P[mi][ni][3] = 0.f;
            }
        }
    }

    __syncthreads();   // done reading A5/W5
    ldW(Bw, g_Wc1h);
    asm volatile("cp.async.commit_group;" ::: "memory");

    // stage Y,Z (fp16) into the dead A region
    __half* Yt = Ah;
    __half* Zt = Ah + 64 * STR;
#pragma unroll
    for (int mi = 0; mi < 2; mi++) {
        int row = rowa + mi * 16;
#pragma unroll
        for (int ni = 0; ni < 4; ni++) {
            int col = wn * 32 + ni * 8 + tg * 2;
            *reinterpret_cast<__half2*>(Yt + row * STR + col) =
                __floats2half2_rn(Y[mi][ni][0], Y[mi][ni][1]);
            *reinterpret_cast<__half2*>(Yt + (row + 8) * STR + col) =
                __floats2half2_rn(Y[mi][ni][2], Y[mi][ni][3]);
            *reinterpret_cast<__half2*>(Zt + row * STR + col) =
                __floats2half2_rn(Z[mi][ni][0], Z[mi][ni][1]);
            *reinterpret_cast<__half2*>(Zt + (row + 8) * STR + col) =
                __floats2half2_rn(Z[mi][ni][2], Z[mi][ni][3]);
        }
    }
    asm volatile("cp.async.wait_group 0;" ::: "memory");
    __syncthreads();

    // stage 2a: P += Y @ Wc1^T
    mmastep(Yt, Bw);
    __syncthreads();   // done reading Wc1
    ldW(Bw, g_Wc2h);
    asm volatile("cp.async.commit_group;" ::: "memory");
    asm volatile("cp.async.wait_group 0;" ::: "memory");
    __syncthreads();
    // stage 2b: P += Z @ Wc2^T
    mmastep(Zt, Bw);

#pragma unroll
    for (int mi = 0; mi < 2; mi++) {
        int ra = n0 + rowa + mi * 16;
#pragma unroll
        for (int ni = 0; ni < 4; ni++) {
            int col = wn * 32 + ni * 8 + tg * 2;
            float b0 = 6.0f * bc[col];
            float b1 = 6.0f * bc[col + 1];
            if (ra < NN) {
                float2 v = make_float2(P[mi][ni][0] + b0, P[mi][ni][1] + b1);
                *reinterpret_cast<float2*>(&out[(size_t)ra * FF + col]) = v;
            }
            if (ra + 8 < NN) {
                float2 v = make_float2(P[mi][ni][2] + b0, P[mi][ni][3] + b1);
                *reinterpret_cast<float2*>(&out[(size_t)(ra + 8) * FF + col]) = v;
            }
        }
    }
}

// ---------------- launch ----------------
extern "C" void kernel_launch(void* const* d_in, const int* in_sizes, int n_in,
                              void* d_out, int out_size) {
    const float* node_h = (const float*)d_in[0];
    const float* W      = (const float*)d_in[1];
    const float* att1   = (const float*)d_in[2];
    const float* att2   = (const float*)d_in[3];
    const float* Wc     = (const float*)d_in[4];
    const float* bc     = (const float*)d_in[5];
    const int*   esrc   = (const int*)d_in[6];
    const int*   edst   = (const int*)d_in[7];
    const int*   erel   = (const int*)d_in[8];
    float* out = (float*)d_out;

    static int inited = 0;
    static cudaStream_t s1;
    static cudaEvent_t evFork, evPre;
    if (!inited) {
        cudaFuncSetAttribute(gemm_kernel, cudaFuncAttributeMaxDynamicSharedMemorySize, GEMM_SMEM);
        cudaStreamCreateWithFlags(&s1, cudaStreamNonBlocking);
        cudaEventCreateWithFlags(&evFork, cudaEventDisableTiming);
        cudaEventCreateWithFlags(&evPre, cudaEventDisableTiming);
        inited = 1;
    }

    const int nblk1 = (SEG + 511) / 512;

    // fork: precompute branch on s1
    cudaEventRecord(evFork, 0);
    cudaStreamWaitEvent(s1, evFork, 0);
    if (out_size >= NN * FF + RR * FF * FF) {
        cudaMemcpyAsync(out + (size_t)NN * FF, W,
                        sizeof(float) * RR * FF * FF, cudaMemcpyDeviceToDevice, s1);
    }
    precompute_kernel<<<RR * FF + FF, 128, 0, s1>>>(W, att1, att2, Wc);
    nodeh_convert_kernel<<<(NN * FF / 8 + 255) / 256, 256, 0, s1>>>(node_h);
    cudaEventRecord(evPre, s1);

    // CSR branch on stream 0 (g_cnt all-zero by invariant)
    hist_kernel<<<(EE / 8 + 255) / 256, 256>>>((const int4*)edst, (const int4*)erel);
    scan1_kernel<<<nblk1, 512>>>();
    scan2_kernel<<<1, 1024>>>(nblk1);
    permute_kernel<<<(EE / 4 + 255) / 256, 256>>>((const int4*)esrc, (const int4*)edst,
                                                  (const int4*)erel);

    cudaStreamWaitEvent(0, evPre, 0);

    gather_kernel<<<(SEG + 7) / 8, 256>>>();
    gemm_kernel<<<(NN + 63) / 64, 256, GEMM_SMEM>>>(out, bc);
}

// round 16
// speedup vs baseline: 1.3563x; 1.1700x over previous
#include <cuda_runtime.h>
#include <cuda_fp16.h>
#include <cstdint>

#define NN 50000
#define EE 800000
#define RR 6
#define FF 128
#define SEG (RR * NN)

// ---------------- scratch (static device globals; no allocations) ----------------
__device__ __align__(16) __half g_nodeH[(size_t)NN * FF];  // 12.8 MB fp16 node_h
__device__ __align__(16) __half g_aggH[(size_t)SEG * FF];  // 76.8 MB fp16 agg
__device__ __align__(16) float g_v1[RR * FF];
__device__ __align__(16) float g_v2[RR * FF];
__device__ __align__(16) __half g_Wh[RR * FF * FF];        // [r][o][f] = W[r][f][o] fp16
__device__ __align__(16) __half g_Wc1h[FF * FF];           // [o][k] fp16
__device__ __align__(16) __half g_Wc2h[FF * FF];
__device__ __align__(16) float g_e1[SEG];
__device__ __align__(16) float g_e2[SEG];
__device__ __align__(16) int g_cnt[SEG];                   // zero-init; invariant: all-zero at launch end
__device__ __align__(16) int g_off[SEG];                   // local (per-512-block) prescan
__device__ __align__(16) int g_bsum[1024];
__device__ __align__(16) int g_src_sorted[EE];

__device__ __forceinline__ void cpa16(void* dst_smem, const void* src) {
    uint32_t d = (uint32_t)__cvta_generic_to_shared(dst_smem);
    asm volatile("cp.async.cg.shared.global [%0], [%1], 16;" :: "r"(d), "l"(src));
}

// ---------------- K0: precompute v1,v2, fp16 W^T, and Wc convert (blocks >= 768) ----------------
__global__ void precompute_kernel(const float* __restrict__ W,
                                  const float* __restrict__ att1,
                                  const float* __restrict__ att2,
                                  const float* __restrict__ Wc) {
    if (blockIdx.x >= RR * FF) {
        int o = blockIdx.x - RR * FF;      // 0..127
        int k = threadIdx.x;
        g_Wc1h[o * FF + k] = __float2half_rn(Wc[o * 256 + k]);
        g_Wc2h[o * FF + k] = __float2half_rn(Wc[o * 256 + 128 + k]);
        return;
    }
    __shared__ float red1[128];
    __shared__ float red2[128];
    int rf = blockIdx.x;           // r*128 + f
    int r  = rf >> 7, f = rf & 127;
    int o  = threadIdx.x;
    float w = W[rf * 128 + o];
    g_Wh[(size_t)r * (FF * FF) + o * FF + f] = __float2half_rn(w);

    red1[o] = w * att1[o];
    red2[o] = w * att2[o];
    __syncthreads();
    for (int s = 64; s > 0; s >>= 1) {
        if (o < s) { red1[o] += red1[o + s]; red2[o] += red2[o + s]; }
        __syncthreads();
    }
    if (o == 0) { g_v1[rf] = red1[0]; g_v2[rf] = red2[0]; }
}

// ---------------- convert node_h -> fp16 ----------------
__global__ void nodeh_convert_kernel(const float* __restrict__ node_h) {
    size_t i = (size_t)blockIdx.x * blockDim.x + threadIdx.x;   // one per 8 elems
    if (i >= (size_t)NN * FF / 8) return;
    const float4* p = reinterpret_cast<const float4*>(node_h) + i * 2;
    float4 a = p[0], b = p[1];
    __half2 h0 = __floats2half2_rn(a.x, a.y);
    __half2 h1 = __floats2half2_rn(a.z, a.w);
    __half2 h2 = __floats2half2_rn(b.x, b.y);
    __half2 h3 = __floats2half2_rn(b.z, b.w);
    uint4 o;
    o.x = *reinterpret_cast<uint32_t*>(&h0);
    o.y = *reinterpret_cast<uint32_t*>(&h1);
    o.z = *reinterpret_cast<uint32_t*>(&h2);
    o.w = *reinterpret_cast<uint32_t*>(&h3);
    reinterpret_cast<uint4*>(g_nodeH)[i] = o;
}

// ---------------- CSR build ----------------
__global__ void hist_kernel(const int4* __restrict__ edst4, const int4* __restrict__ erel4) {
    int i = blockIdx.x * blockDim.x + threadIdx.x;
    if (i >= EE / 8) return;
    int4 d0 = edst4[i * 2], d1 = edst4[i * 2 + 1];
    int4 r0 = erel4[i * 2], r1 = erel4[i * 2 + 1];
    atomicAdd(&g_cnt[r0.x * NN + d0.x], 1);
    atomicAdd(&g_cnt[r0.y * NN + d0.y], 1);
    atomicAdd(&g_cnt[r0.z * NN + d0.z], 1);
    atomicAdd(&g_cnt[r0.w * NN + d0.w], 1);
    atomicAdd(&g_cnt[r1.x * NN + d1.x], 1);
    atomicAdd(&g_cnt[r1.y * NN + d1.y], 1);
    atomicAdd(&g_cnt[r1.z * NN + d1.z], 1);
    atomicAdd(&g_cnt[r1.w * NN + d1.w], 1);
}

// scan1: per-512-block exclusive prescan via warp shuffles
__global__ void scan1_kernel() {
    __shared__ int wsum[16];
    int tid = threadIdx.x;
    int idx = blockIdx.x * 512 + tid;
    int lane = tid & 31, wid = tid >> 5;
    int v = (idx < SEG) ? g_cnt[idx] : 0;
    int incl = v;
#pragma unroll
    for (int s = 1; s < 32; s <<= 1) {
        int u = __shfl_up_sync(0xffffffffu, incl, s);
        if (lane >= s) incl += u;
    }
    if (lane == 31) wsum[wid] = incl;
    __syncthreads();
    if (wid == 0) {
        int wv = (lane < 16) ? wsum[lane] : 0;
        int wi = wv;
#pragma unroll
        for (int s = 1; s < 16; s <<= 1) {
            int u = __shfl_up_sync(0xffffffffu, wi, s);
            if (lane >= s) wi += u;
        }
        if (lane < 16) wsum[lane] = wi - wv;
        if (lane == 15) g_bsum[blockIdx.x] = wi;
    }
    __syncthreads();
    if (idx < SEG) g_off[idx] = incl - v + wsum[wid];
}

// scan2: single block exclusive scan of block sums
__global__ void scan2_kernel(int nblk) {
    __shared__ int wsum[32];
    int tid = threadIdx.x;
    int lane = tid & 31, wid = tid >> 5;
    int v = (tid < nblk) ? g_bsum[tid] : 0;
    int incl = v;
#pragma unroll
    for (int s = 1; s < 32; s <<= 1) {
        int u = __shfl_up_sync(0xffffffffu, incl, s);
        if (lane >= s) incl += u;
    }
    if (lane == 31) wsum[wid] = incl;
    __syncthreads();
    if (wid == 0) {
        int wv = wsum[lane];
        int wi = wv;
#pragma unroll
        for (int s = 1; s < 32; s <<= 1) {
            int u = __shfl_up_sync(0xffffffffu, wi, s);
            if (lane >= s) wi += u;
        }
        wsum[lane] = wi - wv;
    }
    __syncthreads();
    if (tid < nblk) g_bsum[tid] = incl - v + wsum[wid];
}

// permute: final position = local-prescan atomic + block base
__global__ void permute_kernel(const int4* __restrict__ esrc4,
                               const int4* __restrict__ edst4,
                               const int4* __restrict__ erel4) {
    int i = blockIdx.x * blockDim.x + threadIdx.x;
    if (i >= EE / 4) return;
    int4 s = esrc4[i];
    int4 d = edst4[i];
    int4 r = erel4[i];
    int k0 = r.x * NN + d.x;
    int k1 = r.y * NN + d.y;
    int k2 = r.z * NN + d.z;
    int k3 = r.w * NN + d.w;
    int p0 = atomicAdd(&g_off[k0], 1) + g_bsum[k0 >> 9];
    int p1 = atomicAdd(&g_off[k1], 1) + g_bsum[k1 >> 9];
    int p2 = atomicAdd(&g_off[k2], 1) + g_bsum[k2 >> 9];
    int p3 = atomicAdd(&g_off[k3], 1) + g_bsum[k3 >> 9];
    asm volatile("st.global.cs.u32 [%0], %1;" :: "l"(g_src_sorted + p0), "r"(s.x) : "memory");
    asm volatile("st.global.cs.u32 [%0], %1;" :: "l"(g_src_sorted + p1), "r"(s.y) : "memory");
    asm volatile("st.global.cs.u32 [%0], %1;" :: "l"(g_src_sorted + p2), "r"(s.z) : "memory");
    asm volatile("st.global.cs.u32 [%0], %1;" :: "l"(g_src_sorted + p3), "r"(s.w) : "memory");
}

// ---------------- gather: one warp per (rel,dst) segment; fp16 in, fp16 out ----------------
__global__ __launch_bounds__(256) void gather_kernel() {
    int seg = blockIdx.x * 8 + (threadIdx.x >> 5);
    if (seg >= SEG) return;
    int l = threadIdx.x & 31;
    int r = seg / NN;
    int deg = g_cnt[seg];
    int off = g_off[seg] + g_bsum[seg >> 9] - deg;   // post-permute base

    const uint2* h2 = reinterpret_cast<const uint2*>(g_nodeH);
    float4 acc = make_float4(0.f, 0.f, 0.f, 0.f);
    int e = 0;
    for (; e + 4 <= deg; e += 4) {
        int i0 = g_src_sorted[off + e];
        int i1 = g_src_sorted[off + e + 1];
        int i2 = g_src_sorted[off + e + 2];
        int i3 = g_src_sorted[off + e + 3];
        uint2 u0 = h2[(size_t)i0 * 32 + l];
        uint2 u1 = h2[(size_t)i1 * 32 + l];
        uint2 u2 = h2[(size_t)i2 * 32 + l];
        uint2 u3 = h2[(size_t)i3 * 32 + l];
        float2 a0 = __half22float2(*reinterpret_cast<__half2*>(&u0.x));
        float2 a1 = __half22float2(*reinterpret_cast<__half2*>(&u0.y));
        float2 b0 = __half22float2(*reinterpret_cast<__half2*>(&u1.x));
        float2 b1 = __half22float2(*reinterpret_cast<__half2*>(&u1.y));
        float2 c0 = __half22float2(*reinterpret_cast<__half2*>(&u2.x));
        float2 c1 = __half22float2(*reinterpret_cast<__half2*>(&u2.y));
        float2 d0 = __half22float2(*reinterpret_cast<__half2*>(&u3.x));
        float2 d1 = __half22float2(*reinterpret_cast<__half2*>(&u3.y));
        acc.x += (a0.x + b0.x) + (c0.x + d0.x);
        acc.y += (a0.y + b0.y) + (c0.y + d0.y);
        acc.z += (a1.x + b1.x) + (c1.x + d1.x);
        acc.w += (a1.y + b1.y) + (c1.y + d1.y);
    }
    for (; e < deg; e++) {
        int i0 = g_src_sorted[off + e];
        uint2 ua = h2[(size_t)i0 * 32 + l];
        float2 a0 = __half22float2(*reinterpret_cast<__half2*>(&ua.x));
        float2 a1 = __half22float2(*reinterpret_cast<__half2*>(&ua.y));
        acc.x += a0.x; acc.y += a0.y; acc.z += a1.x; acc.w += a1.y;
    }

    __half2 h01 = __floats2half2_rn(acc.x, acc.y);
    __half2 h23 = __floats2half2_rn(acc.z, acc.w);
    uint32_t px = *reinterpret_cast<uint32_t*>(&h01);
    uint32_t py = *reinterpret_cast<uint32_t*>(&h23);
    // evict-first streaming store: keep node_h resident in L2
    asm volatile("st.global.cs.v2.u32 [%0], {%1,%2};"
                 :: "l"(reinterpret_cast<uint2*>(g_aggH) + (size_t)seg * 32 + l),
                    "r"(px), "r"(py) : "memory");

    float4 w1 = reinterpret_cast<const float4*>(g_v1)[r * 32 + l];
    float4 w2 = reinterpret_cast<const float4*>(g_v2)[r * 32 + l];
    float p1 = acc.x * w1.x + acc.y * w1.y + acc.z * w1.z + acc.w * w1.w;
    float p2 = acc.x * w2.x + acc.y * w2.y + acc.z * w2.z + acc.w * w2.w;
#pragma unroll
    for (int s = 16; s > 0; s >>= 1) {
        p1 += __shfl_xor_sync(0xffffffffu, p1, s);
        p2 += __shfl_xor_sync(0xffffffffu, p2, s);
    }
    if (l == 0) { g_e1[seg] = p1; g_e2[seg] = p2; }
}

// ---------------- K4: fused softmax + factored GEMM (2 blocks/SM) ----------------
__device__ __forceinline__ void mma16(float d[4], uint32_t a0, uint32_t a1, uint32_t a2, uint32_t a3,
                                      uint32_t b0, uint32_t b1) {
    asm volatile(
        "mma.sync.aligned.m16n8k16.row.col.f32.f16.f16.f32 "
        "{%0,%1,%2,%3},{%4,%5,%6,%7},{%8,%9},{%0,%1,%2,%3};"
        : "+f"(d[0]), "+f"(d[1]), "+f"(d[2]), "+f"(d[3])
        : "r"(a0), "r"(a1), "r"(a2), "r"(a3), "r"(b0), "r"(b1));
}

#define STR 136
#define AH_OFF 0
#define BW_OFF (2 * 64 * STR)
#define WC2_OFF (BW_OFF + 128 * STR)
#define CS_OFF (WC2_OFF + 128 * STR)
#define GEMM_SMEM (CS_OFF * 2 + 768 * 4) // 107520 bytes

__global__ __launch_bounds__(256, 2) void gemm_kernel(float* __restrict__ out,
                                                      const float* __restrict__ bc) {
    extern __shared__ __half sh[];
    __half* Ah   = sh + AH_OFF;
    __half* Bw   = sh + BW_OFF;
    __half* Wc2s = sh + WC2_OFF;
    float* c1s = reinterpret_cast<float*>(sh + CS_OFF);
    float* c2s = c1s + 384;

    int n0 = blockIdx.x * 64;
    int t = threadIdx.x;
    int warp = t >> 5, lane = t & 31;
    int wm = warp >> 2, wn = warp & 3;
    int g = lane >> 2, tg = lane & 3;
    int rowa = wm * 32 + g;

    auto ldA = [&](int s, int buf) {
#pragma unroll
        for (int j = 0; j < 4; j++) {
            int lin = t + 256 * j;
            int row = lin >> 4;
            int c8 = (lin & 15) * 8;
            int n = n0 + row;
            if (n >= NN) n = 0;
            cpa16(Ah + buf * 64 * STR + row * STR + c8,
                  g_aggH + ((size_t)s * NN + n) * FF + c8);
        }
    };
    auto ldW = [&](__half* dst, const __half* src) {
#pragma unroll
        for (int j = 0; j < 8; j++) {
            int lin = t + 256 * j;
            int o = lin >> 4;
            int c8 = (lin & 15) * 8;
            cpa16(dst + o * STR + c8, src + o * FF + c8);
        }
    };

    // prologue: G0 = {A0, W0}, G1 = {A1}
    ldA(0, 0); ldW(Bw, g_Wh);
    asm volatile("cp.async.commit_group;" ::: "memory");
    ldA(1, 1);
    asm volatile("cp.async.commit_group;" ::: "memory");

    // fused softmax: threads 0..63, one node each; zero g_cnt afterwards
    if (t < 64) {
        int n = n0 + t;
        if (n < NN) {
            float e1[RR], e2[RR], dg[RR];
#pragma unroll
            for (int r = 0; r < RR; r++) {
                dg[r] = 1.0f + (float)g_cnt[r * NN + n];
                e1[r] = g_e1[r * NN + n] / dg[r];
                e2[r] = g_e2[r * NN + n] / dg[r];
            }
#pragma unroll
            for (int r = 0; r < RR; r++) g_cnt[r * NN + n] = 0;
            float m1 = e1[0], m2 = e2[0];
#pragma unroll
            for (int r = 1; r < RR; r++) { m1 = fmaxf(m1, e1[r]); m2 = fmaxf(m2, e2[r]); }
            float s1 = 0.f, s2 = 0.f;
#pragma unroll
            for (int r = 0; r < RR; r++) {
                e1[r] = __expf(e1[r] - m1); s1 += e1[r];
                e2[r] = __expf(e2[r] - m2); s2 += e2[r];
            }
            float i1 = 1.0f / s1, i2 = 1.0f / s2;
#pragma unroll
            for (int r = 0; r < RR; r++) {
                c1s[t * 6 + r] = e1[r] * i1 / dg[r];
                c2s[t * 6 + r] = e2[r] * i2 / dg[r];
            }
        } else {
#pragma unroll
            for (int r = 0; r < RR; r++) { c1s[t * 6 + r] = 0.f; c2s[t * 6 + r] = 0.f; }
        }
    }

    float P[2][4][4], Y[2][4][4], Z[2][4][4];
#pragma unroll
    for (int mi = 0; mi < 2; mi++)
#pragma unroll
        for (int ni = 0; ni < 4; ni++)
#pragma unroll
            for (int j = 0; j < 4; j++) { P[mi][ni][j] = 0.f; Y[mi][ni][j] = 0.f; Z[mi][ni][j] = 0.f; }

    auto mmastep = [&](const __half* Abase, const __half* Bbase) {
#pragma unroll
        for (int ks = 0; ks < 8; ks++) {
            int k0 = ks * 16;
            uint32_t a[2][4];
#pragma unroll
            for (int mi = 0; mi < 2; mi++) {
                const __half* ap = Abase + (rowa + mi * 16) * STR + k0 + tg * 2;
                a[mi][0] = *reinterpret_cast<const uint32_t*>(ap);
                a[mi][1] = *reinterpret_cast<const uint32_t*>(ap + 8 * STR);
                a[mi][2] = *reinterpret_cast<const uint32_t*>(ap + 8);
                a[mi][3] = *reinterpret_cast<const uint32_t*>(ap + 8 * STR + 8);
            }
            uint32_t b[4][2];
#pragma unroll
            for (int ni = 0; ni < 4; ni++) {
                const __half* bp = Bbase + (wn * 32 + ni * 8 + g) * STR + k0 + tg * 2;
                b[ni][0] = *reinterpret_cast<const uint32_t*>(bp);
                b[ni][1] = *reinterpret_cast<const uint32_t*>(bp + 8);
            }
#pragma unroll
            for (int mi = 0; mi < 2; mi++)
#pragma unroll
                for (int ni = 0; ni < 4; ni++)
                    mma16(P[mi][ni], a[mi][0], a[mi][1], a[mi][2], a[mi][3],
                          b[ni][0], b[ni][1]);
        }
    };

    for (int s = 0; s < 6; s++) {
        if (s == 5) { asm volatile("cp.async.wait_group 0;" ::: "memory"); }
        else        { asm volatile("cp.async.wait_group 1;" ::: "memory"); }
        __syncthreads();
        mmastep(Ah + (s & 1) * 64 * STR, Bw);
        if (s < 5) {
            __syncthreads();
            ldW(Bw, g_Wh + (size_t)(s + 1) * (FF * FF));
            asm volatile("cp.async.commit_group;" ::: "memory");
            if (s + 2 < 6) {
                ldA(s + 2, s & 1);
                asm volatile("cp.async.commit_group;" ::: "memory");
            }
        }
#pragma unroll
        for (int mi = 0; mi < 2; mi++) {
            int rl = rowa + mi * 16;
            float c1a = c1s[rl * 6 + s];
            float c1b = c1s[(rl + 8) * 6 + s];
            float c2a = c2s[rl * 6 + s];
            float c2b = c2s[(rl + 8) * 6 + s];
#pragma unroll
            for (int ni = 0; ni < 4; ni++) {
                Y[mi][ni][0] += c1a * P[mi][ni][0];
                Y[mi][ni][1] += c1a * P[mi][ni][1];
                Y[mi][ni][2] += c1b * P[mi][ni][2];
                Y[mi][ni][3] += c1b * P[mi][ni][3];
                Z[mi][ni][0] += c2a * P[mi][ni][0];
                Z[mi][ni][1] += c2a * P[mi][ni][1];
                Z[mi][ni][2] += c2b * P[mi][ni][2];
                Z[mi][ni][3] += c2b * P[mi][ni][3];
                P[mi][ni][0] = 0.f; P[mi][ni][1] = 0.f;
                P[mi][ni][2] = 0.f; P[mi][ni][3] = 0.f;
            }
        }
    }

    __syncthreads();
    ldW(Bw, g_Wc1h);
    ldW(Wc2s, g_Wc2h);
    asm volatile("cp.async.commit_group;" ::: "memory");

    __half* Yt = Ah;
    __half* Zt = Ah + 64 * STR;
#pragma unroll
    for (int mi = 0; mi < 2; mi++) {
        int row = rowa + mi * 16;
#pragma unroll
        for (int ni = 0; ni < 4; ni++) {
            int col = wn * 32 + ni * 8 + tg * 2;
            *reinterpret_cast<__half2*>(Yt + row * STR + col) =
                __floats2half2_rn(Y[mi][ni][0], Y[mi][ni][1]);
            *reinterpret_cast<__half2*>(Yt + (row + 8) * STR + col) =
                __floats2half2_rn(Y[mi][ni][2], Y[mi][ni][3]);
            *reinterpret_cast<__half2*>(Zt + row * STR + col) =
                __floats2half2_rn(Z[mi][ni][0], Z[mi][ni][1]);
            *reinterpret_cast<__half2*>(Zt + (row + 8) * STR + col) =
                __floats2half2_rn(Z[mi][ni][2], Z[mi][ni][3]);
        }
    }
    asm volatile("cp.async.wait_group 0;" ::: "memory");
    __syncthreads();

    mmastep(Yt, Bw);
    mmastep(Zt, Wc2s);

#pragma unroll
    for (int mi = 0; mi < 2; mi++) {
        int ra = n0 + rowa + mi * 16;
#pragma unroll
        for (int ni = 0; ni < 4; ni++) {
            int col = wn * 32 + ni * 8 + tg * 2;
            float b0 = 6.0f * bc[col];
            float b1 = 6.0f * bc[col + 1];
            if (ra < NN) {
                float2 v = make_float2(P[mi][ni][0] + b0, P[mi][ni][1] + b1);
                *reinterpret_cast<float2*>(&out[(size_t)ra * FF + col]) = v;
            }
            if (ra + 8 < NN) {
                float2 v = make_float2(P[mi][ni][2] + b0, P[mi][ni][3] + b1);
                *reinterpret_cast<float2*>(&out[(size_t)(ra + 8) * FF + col]) = v;
            }
        }
    }
}

// ---------------- launch ----------------
extern "C" void kernel_launch(void* const* d_in, const int* in_sizes, int n_in,
                              void* d_out, int out_size) {
    const float* node_h = (const float*)d_in[0];
    const float* W      = (const float*)d_in[1];
    const float* att1   = (const float*)d_in[2];
    const float* att2   = (const float*)d_in[3];
    const float* Wc     = (const float*)d_in[4];
    const float* bc     = (const float*)d_in[5];
    const int*   esrc   = (const int*)d_in[6];
    const int*   edst   = (const int*)d_in[7];
    const int*   erel   = (const int*)d_in[8];
    float* out = (float*)d_out;

    static int inited = 0;
    static cudaStream_t s1;
    static cudaEvent_t evFork, evPre;
    if (!inited) {
        cudaFuncSetAttribute(gemm_kernel, cudaFuncAttributeMaxDynamicSharedMemorySize, GEMM_SMEM);
        cudaStreamCreateWithFlags(&s1, cudaStreamNonBlocking);
        cudaEventCreateWithFlags(&evFork, cudaEventDisableTiming);
        cudaEventCreateWithFlags(&evPre, cudaEventDisableTiming);
        inited = 1;
    }

    const int nblk1 = (SEG + 511) / 512;   // 586

    // fork: precompute branch on s1 (independent of CSR build)
    cudaEventRecord(evFork, 0);
    cudaStreamWaitEvent(s1, evFork, 0);
    if (out_size >= NN * FF + RR * FF * FF) {
        cudaMemcpyAsync(out + (size_t)NN * FF, W,
                        sizeof(float) * RR * FF * FF, cudaMemcpyDeviceToDevice, s1);
    }
    precompute_kernel<<<RR * FF + FF, 128, 0, s1>>>(W, att1, att2, Wc);
    nodeh_convert_kernel<<<(NN * FF / 8 + 255) / 256, 256, 0, s1>>>(node_h);
    cudaEventRecord(evPre, s1);

    // CSR branch on stream 0 (g_cnt is all-zero: static init / restored by gemm)
    hist_kernel<<<(EE / 8 + 255) / 256, 256>>>((const int4*)edst, (const int4*)erel);
    scan1_kernel<<<nblk1, 512>>>();
    scan2_kernel<<<1, 1024>>>(nblk1);
    permute_kernel<<<(EE / 4 + 255) / 256, 256>>>((const int4*)esrc, (const int4*)edst,
                                                  (const int4*)erel);

    // join precompute before gather
    cudaStreamWaitEvent(0, evPre, 0);

    gather_kernel<<<(SEG + 7) / 8, 256>>>();
    gemm_kernel<<<(NN + 63) / 64, 256, GEMM_SMEM>>>(out, bc);
}

// round 17
// speedup vs baseline: 1.4249x; 1.0506x over previous
#include <cuda_runtime.h>
#include <cuda_fp16.h>
#include <cstdint>

#define NN 50000
#define EE 800000
#define RR 6
#define FF 128
#define SEG (RR * NN)

// ---------------- scratch (static device globals; no allocations) ----------------
__device__ __align__(16) __half g_nodeH[(size_t)NN * FF];  // 12.8 MB fp16 node_h
__device__ __align__(16) __half g_aggH[(size_t)SEG * FF];  // 76.8 MB fp16 agg
__device__ __align__(16) float g_v1[RR * FF];
__device__ __align__(16) float g_v2[RR * FF];
__device__ __align__(16) __half g_Wh[RR * FF * FF];        // [r][o][f] = W[r][f][o] fp16
__device__ __align__(16) __half g_Wc1h[FF * FF];           // [o][k] fp16
__device__ __align__(16) __half g_Wc2h[FF * FF];
__device__ __align__(16) float g_e1[SEG];
__device__ __align__(16) float g_e2[SEG];
__device__ __align__(16) int g_cnt[SEG];                   // zero-init; invariant: all-zero at launch end
__device__ __align__(16) int g_off[SEG];                   // local (per-512-block) prescan
__device__ __align__(16) int g_bsum[1024];
__device__ __align__(16) int g_src_sorted[EE];

__device__ __forceinline__ void cpa16(void* dst_smem, const void* src) {
    uint32_t d = (uint32_t)__cvta_generic_to_shared(dst_smem);
    asm volatile("cp.async.cg.shared.global [%0], [%1], 16;" :: "r"(d), "l"(src));
}

// ---------------- K0: precompute v1,v2, fp16 W^T, and Wc convert (blocks >= 768) ----------------
__global__ void precompute_kernel(const float* __restrict__ W,
                                  const float* __restrict__ att1,
                                  const float* __restrict__ att2,
                                  const float* __restrict__ Wc) {
    if (blockIdx.x >= RR * FF) {
        int o = blockIdx.x - RR * FF;      // 0..127
        int k = threadIdx.x;
        g_Wc1h[o * FF + k] = __float2half_rn(Wc[o * 256 + k]);
        g_Wc2h[o * FF + k] = __float2half_rn(Wc[o * 256 + 128 + k]);
        return;
    }
    __shared__ float red1[128];
    __shared__ float red2[128];
    int rf = blockIdx.x;           // r*128 + f
    int r  = rf >> 7, f = rf & 127;
    int o  = threadIdx.x;
    float w = W[rf * 128 + o];
    g_Wh[(size_t)r * (FF * FF) + o * FF + f] = __float2half_rn(w);

    red1[o] = w * att1[o];
    red2[o] = w * att2[o];
    __syncthreads();
    for (int s = 64; s > 0; s >>= 1) {
        if (o < s) { red1[o] += red1[o + s]; red2[o] += red2[o + s]; }
        __syncthreads();
    }
    if (o == 0) { g_v1[rf] = red1[0]; g_v2[rf] = red2[0]; }
}

// ---------------- convert node_h -> fp16 ----------------
__global__ void nodeh_convert_kernel(const float* __restrict__ node_h) {
    size_t i = (size_t)blockIdx.x * blockDim.x + threadIdx.x;   // one per 8 elems
    if (i >= (size_t)NN * FF / 8) return;
    const float4* p = reinterpret_cast<const float4*>(node_h) + i * 2;
    float4 a = p[0], b = p[1];
    __half2 h0 = __floats2half2_rn(a.x, a.y);
    __half2 h1 = __floats2half2_rn(a.z, a.w);
    __half2 h2 = __floats2half2_rn(b.x, b.y);
    __half2 h3 = __floats2half2_rn(b.z, b.w);
    uint4 o;
    o.x = *reinterpret_cast<uint32_t*>(&h0);
    o.y = *reinterpret_cast<uint32_t*>(&h1);
    o.z = *reinterpret_cast<uint32_t*>(&h2);
    o.w = *reinterpret_cast<uint32_t*>(&h3);
    reinterpret_cast<uint4*>(g_nodeH)[i] = o;
}

// ---------------- CSR build ----------------
__global__ void hist_kernel(const int4* __restrict__ edst4, const int4* __restrict__ erel4) {
    int i = blockIdx.x * blockDim.x + threadIdx.x;
    if (i >= EE / 8) return;
    int4 d0 = edst4[i * 2], d1 = edst4[i * 2 + 1];
    int4 r0 = erel4[i * 2], r1 = erel4[i * 2 + 1];
    atomicAdd(&g_cnt[r0.x * NN + d0.x], 1);
    atomicAdd(&g_cnt[r0.y * NN + d0.y], 1);
    atomicAdd(&g_cnt[r0.z * NN + d0.z], 1);
    atomicAdd(&g_cnt[r0.w * NN + d0.w], 1);
    atomicAdd(&g_cnt[r1.x * NN + d1.x], 1);
    atomicAdd(&g_cnt[r1.y * NN + d1.y], 1);
    atomicAdd(&g_cnt[r1.z * NN + d1.z], 1);
    atomicAdd(&g_cnt[r1.w * NN + d1.w], 1);
}

// scan1: per-512-block exclusive prescan via warp shuffles
__global__ void scan1_kernel() {
    __shared__ int wsum[16];
    int tid = threadIdx.x;
    int idx = blockIdx.x * 512 + tid;
    int lane = tid & 31, wid = tid >> 5;
    int v = (idx < SEG) ? g_cnt[idx] : 0;
    int incl = v;
#pragma unroll
    for (int s = 1; s < 32; s <<= 1) {
        int u = __shfl_up_sync(0xffffffffu, incl, s);
        if (lane >= s) incl += u;
    }
    if (lane == 31) wsum[wid] = incl;
    __syncthreads();
    if (wid == 0) {
        int wv = (lane < 16) ? wsum[lane] : 0;
        int wi = wv;
#pragma unroll
        for (int s = 1; s < 16; s <<= 1) {
            int u = __shfl_up_sync(0xffffffffu, wi, s);
            if (lane >= s) wi += u;
        }
        if (lane < 16) wsum[lane] = wi - wv;
        if (lane == 15) g_bsum[blockIdx.x] = wi;
    }
    __syncthreads();
    if (idx < SEG) g_off[idx] = incl - v + wsum[wid];
}

// scan2: single block exclusive scan of block sums
__global__ void scan2_kernel(int nblk) {
    __shared__ int wsum[32];
    int tid = threadIdx.x;
    int lane = tid & 31, wid = tid >> 5;
    int v = (tid < nblk) ? g_bsum[tid] : 0;
    int incl = v;
#pragma unroll
    for (int s = 1; s < 32; s <<= 1) {
        int u = __shfl_up_sync(0xffffffffu, incl, s);
        if (lane >= s) incl += u;
    }
    if (lane == 31) wsum[wid] = incl;
    __syncthreads();
    if (wid == 0) {
        int wv = wsum[lane];
        int wi = wv;
#pragma unroll
        for (int s = 1; s < 32; s <<= 1) {
            int u = __shfl_up_sync(0xffffffffu, wi, s);
            if (lane >= s) wi += u;
        }
        wsum[lane] = wi - wv;
    }
    __syncthreads();
    if (tid < nblk) g_bsum[tid] = incl - v + wsum[wid];
}

// permute: final position = local-prescan atomic + block base
__global__ void permute_kernel(const int4* __restrict__ esrc4,
                               const int4* __restrict__ edst4,
                               const int4* __restrict__ erel4) {
    int i = blockIdx.x * blockDim.x + threadIdx.x;
    if (i >= EE / 4) return;
    int4 s = esrc4[i];
    int4 d = edst4[i];
    int4 r = erel4[i];
    int k0 = r.x * NN + d.x;
    int k1 = r.y * NN + d.y;
    int k2 = r.z * NN + d.z;
    int k3 = r.w * NN + d.w;
    int p0 = atomicAdd(&g_off[k0], 1) + g_bsum[k0 >> 9];
    int p1 = atomicAdd(&g_off[k1], 1) + g_bsum[k1 >> 9];
    int p2 = atomicAdd(&g_off[k2], 1) + g_bsum[k2 >> 9];
    int p3 = atomicAdd(&g_off[k3], 1) + g_bsum[k3 >> 9];
    asm volatile("st.global.cs.u32 [%0], %1;" :: "l"(g_src_sorted + p0), "r"(s.x) : "memory");
    asm volatile("st.global.cs.u32 [%0], %1;" :: "l"(g_src_sorted + p1), "r"(s.y) : "memory");
    asm volatile("st.global.cs.u32 [%0], %1;" :: "l"(g_src_sorted + p2), "r"(s.z) : "memory");
    asm volatile("st.global.cs.u32 [%0], %1;" :: "l"(g_src_sorted + p3), "r"(s.w) : "memory");
}

// ---------------- gather: HALF-WARP (16 lanes) per segment; uint4 (16B) loads ----------------
__global__ __launch_bounds__(256) void gather_kernel() {
    int seg = blockIdx.x * 16 + (threadIdx.x >> 4);
    if (seg >= SEG) return;
    int l = threadIdx.x & 15;          // lane within half-warp; 16 x 16B = 256B row
    int r = seg / NN;
    int deg = g_cnt[seg];
    int off = g_off[seg] + g_bsum[seg >> 9] - deg;   // post-permute base

    const uint4* h4 = reinterpret_cast<const uint4*>(g_nodeH);   // 16 uint4 per row
    float a0 = 0.f, a1 = 0.f, a2 = 0.f, a3 = 0.f;
    float a4 = 0.f, a5 = 0.f, a6 = 0.f, a7 = 0.f;

    int e = 0;
    for (; e + 4 <= deg; e += 4) {
        int i0 = g_src_sorted[off + e];
        int i1 = g_src_sorted[off + e + 1];
        int i2 = g_src_sorted[off + e + 2];
        int i3 = g_src_sorted[off + e + 3];
        uint4 u0 = h4[(size_t)i0 * 16 + l];
        uint4 u1 = h4[(size_t)i1 * 16 + l];
        uint4 u2 = h4[(size_t)i2 * 16 + l];
        uint4 u3 = h4[(size_t)i3 * 16 + l];
#pragma unroll
        for (int q = 0; q < 4; q++) {
            uint32_t w0 = (&u0.x)[q], w1 = (&u1.x)[q], w2 = (&u2.x)[q], w3 = (&u3.x)[q];
            float2 f0 = __half22float2(*reinterpret_cast<__half2*>(&w0));
            float2 f1 = __half22float2(*reinterpret_cast<__half2*>(&w1));
            float2 f2 = __half22float2(*reinterpret_cast<__half2*>(&w2));
            float2 f3 = __half22float2(*reinterpret_cast<__half2*>(&w3));
            float sx = (f0.x + f1.x) + (f2.x + f3.x);
            float sy = (f0.y + f1.y) + (f2.y + f3.y);
            if (q == 0) { a0 += sx; a1 += sy; }
            else if (q == 1) { a2 += sx; a3 += sy; }
            else if (q == 2) { a4 += sx; a5 += sy; }
            else { a6 += sx; a7 += sy; }
        }
    }
    for (; e < deg; e++) {
        int i0 = g_src_sorted[off + e];
        uint4 u0 = h4[(size_t)i0 * 16 + l];
#pragma unroll
        for (int q = 0; q < 4; q++) {
            uint32_t w0 = (&u0.x)[q];
            float2 f0 = __half22float2(*reinterpret_cast<__half2*>(&w0));
            if (q == 0) { a0 += f0.x; a1 += f0.y; }
            else if (q == 1) { a2 += f0.x; a3 += f0.y; }
            else if (q == 2) { a4 += f0.x; a5 += f0.y; }
            else { a6 += f0.x; a7 += f0.y; }
        }
    }

    // pack and store 16B (evict-first streaming: keep node_h resident in L2)
    __half2 o0 = __floats2half2_rn(a0, a1);
    __half2 o1 = __floats2half2_rn(a2, a3);
    __half2 o2 = __floats2half2_rn(a4, a5);
    __half2 o3 = __floats2half2_rn(a6, a7);
    asm volatile("st.global.cs.v4.u32 [%0], {%1,%2,%3,%4};"
                 :: "l"(reinterpret_cast<uint4*>(g_aggH) + (size_t)seg * 16 + l),
                    "r"(*reinterpret_cast<uint32_t*>(&o0)),
                    "r"(*reinterpret_cast<uint32_t*>(&o1)),
                    "r"(*reinterpret_cast<uint32_t*>(&o2)),
                    "r"(*reinterpret_cast<uint32_t*>(&o3)) : "memory");

    // attention dots: lane l covers features [l*8, l*8+8)
    const float4* v1p = reinterpret_cast<const float4*>(g_v1 + r * FF + l * 8);
    const float4* v2p = reinterpret_cast<const float4*>(g_v2 + r * FF + l * 8);
    float4 w10 = v1p[0], w11 = v1p[1];
    float4 w20 = v2p[0], w21 = v2p[1];
    float p1 = a0 * w10.x + a1 * w10.y + a2 * w10.z + a3 * w10.w
             + a4 * w11.x + a5 * w11.y + a6 * w11.z + a7 * w11.w;
    float p2 = a0 * w20.x + a1 * w20.y + a2 * w20.z + a3 * w20.w
             + a4 * w21.x + a5 * w21.y + a6 * w21.z + a7 * w21.w;
#pragma unroll
    for (int s = 8; s > 0; s >>= 1) {     // xor-shuffles stay within the aligned 16-lane half
        p1 += __shfl_xor_sync(0xffffffffu, p1, s);
        p2 += __shfl_xor_sync(0xffffffffu, p2, s);
    }
    if (l == 0) { g_e1[seg] = p1; g_e2[seg] = p2; }
}

// ---------------- K4: fused softmax + factored GEMM (2 blocks/SM) ----------------
__device__ __forceinline__ void mma16(float d[4], uint32_t a0, uint32_t a1, uint32_t a2, uint32_t a3,
                                      uint32_t b0, uint32_t b1) {
    asm volatile(
        "mma.sync.aligned.m16n8k16.row.col.f32.f16.f16.f32 "
        "{%0,%1,%2,%3},{%4,%5,%6,%7},{%8,%9},{%0,%1,%2,%3};"
        : "+f"(d[0]), "+f"(d[1]), "+f"(d[2]), "+f"(d[3])
        : "r"(a0), "r"(a1), "r"(a2), "r"(a3), "r"(b0), "r"(b1));
}

#define STR 136
#define AH_OFF 0
#define BW_OFF (2 * 64 * STR)
#define WC2_OFF (BW_OFF + 128 * STR)
#define CS_OFF (WC2_OFF + 128 * STR)
#define GEMM_SMEM (CS_OFF * 2 + 768 * 4) // 107520 bytes

__global__ __launch_bounds__(256, 2) void gemm_kernel(float* __restrict__ out,
                                                      const float* __restrict__ bc) {
    extern __shared__ __half sh[];
    __half* Ah   = sh + AH_OFF;
    __half* Bw   = sh + BW_OFF;
    __half* Wc2s = sh + WC2_OFF;
    float* c1s = reinterpret_cast<float*>(sh + CS_OFF);
    float* c2s = c1s + 384;

    int n0 = blockIdx.x * 64;
    int t = threadIdx.x;
    int warp = t >> 5, lane = t & 31;
    int wm = warp >> 2, wn = warp & 3;
    int g = lane >> 2, tg = lane & 3;
    int rowa = wm * 32 + g;

    auto ldA = [&](int s, int buf) {
#pragma unroll
        for (int j = 0; j < 4; j++) {
            int lin = t + 256 * j;
            int row = lin >> 4;
            int c8 = (lin & 15) * 8;
            int n = n0 + row;
            if (n >= NN) n = 0;
            cpa16(Ah + buf * 64 * STR + row * STR + c8,
                  g_aggH + ((size_t)s * NN + n) * FF + c8);
        }
    };
    auto ldW = [&](__half* dst, const __half* src) {
#pragma unroll
        for (int j = 0; j < 8; j++) {
            int lin = t + 256 * j;
            int o = lin >> 4;
            int c8 = (lin & 15) * 8;
            cpa16(dst + o * STR + c8, src + o * FF + c8);
        }
    };

    // prologue: G0 = {A0, W0}, G1 = {A1}
    ldA(0, 0); ldW(Bw, g_Wh);
    asm volatile("cp.async.commit_group;" ::: "memory");
    ldA(1, 1);
    asm volatile("cp.async.commit_group;" ::: "memory");

    // fused softmax: threads 0..63, one node each; zero g_cnt afterwards
    if (t < 64) {
        int n = n0 + t;
        if (n < NN) {
            float e1[RR], e2[RR], dg[RR];
#pragma unroll
            for (int r = 0; r < RR; r++) {
                dg[r] = 1.0f + (float)g_cnt[r * NN + n];
                e1[r] = g_e1[r * NN + n] / dg[r];
                e2[r] = g_e2[r * NN + n] / dg[r];
            }
#pragma unroll
            for (int r = 0; r < RR; r++) g_cnt[r * NN + n] = 0;
            float m1 = e1[0], m2 = e2[0];
#pragma unroll
            for (int r = 1; r < RR; r++) { m1 = fmaxf(m1, e1[r]); m2 = fmaxf(m2, e2[r]); }
            float s1 = 0.f, s2 = 0.f;
#pragma unroll
            for (int r = 0; r < RR; r++) {
                e1[r] = __expf(e1[r] - m1); s1 += e1[r];
                e2[r] = __expf(e2[r] - m2); s2 += e2[r];
            }
            float i1 = 1.0f / s1, i2 = 1.0f / s2;
#pragma unroll
            for (int r = 0; r < RR; r++) {
                c1s[t * 6 + r] = e1[r] * i1 / dg[r];
                c2s[t * 6 + r] = e2[r] * i2 / dg[r];
            }
        } else {
#pragma unroll
            for (int r = 0; r < RR; r++) { c1s[t * 6 + r] = 0.f; c2s[t * 6 + r] = 0.f; }
        }
    }

    float P[2][4][4], Y[2][4][4], Z[2][4][4];
#pragma unroll
    for (int mi = 0; mi < 2; mi++)
#pragma unroll
        for (int ni = 0; ni < 4; ni++)
#pragma unroll
            for (int j = 0; j < 4; j++) { P[mi][ni][j] = 0.f; Y[mi][ni][j] = 0.f; Z[mi][ni][j] = 0.f; }

    auto mmastep = [&](const __half* Abase, const __half* Bbase) {
#pragma unroll
        for (int ks = 0; ks < 8; ks++) {
            int k0 = ks * 16;
            uint32_t a[2][4];
#pragma unroll
            for (int mi = 0; mi < 2; mi++) {
                const __half* ap = Abase + (rowa + mi * 16) * STR + k0 + tg * 2;
                a[mi][0] = *reinterpret_cast<const uint32_t*>(ap);
                a[mi][1] = *reinterpret_cast<const uint32_t*>(ap + 8 * STR);
                a[mi][2] = *reinterpret_cast<const uint32_t*>(ap + 8);
                a[mi][3] = *reinterpret_cast<const uint32_t*>(ap + 8 * STR + 8);
            }
            uint32_t b[4][2];
#pragma unroll
            for (int ni = 0; ni < 4; ni++) {
                const __half* bp = Bbase + (wn * 32 + ni * 8 + g) * STR + k0 + tg * 2;
                b[ni][0] = *reinterpret_cast<const uint32_t*>(bp);
                b[ni][1] = *reinterpret_cast<const uint32_t*>(bp + 8);
            }
#pragma unroll
            for (int mi = 0; mi < 2; mi++)
#pragma unroll
                for (int ni = 0; ni < 4; ni++)
                    mma16(P[mi][ni], a[mi][0], a[mi][1], a[mi][2], a[mi][3],
                          b[ni][0], b[ni][1]);
        }
    };

    for (int s = 0; s < 6; s++) {
        if (s == 5) { asm volatile("cp.async.wait_group 0;" ::: "memory"); }
        else        { asm volatile("cp.async.wait_group 1;" ::: "memory"); }
        __syncthreads();
        mmastep(Ah + (s & 1) * 64 * STR, Bw);
        if (s < 5) {
            __syncthreads();
            ldW(Bw, g_Wh + (size_t)(s + 1) * (FF * FF));
            asm volatile("cp.async.commit_group;" ::: "memory");
            if (s + 2 < 6) {
                ldA(s + 2, s & 1);
                asm volatile("cp.async.commit_group;" ::: "memory");
            }
        }
#pragma unroll
        for (int mi = 0; mi < 2; mi++) {
            int rl = rowa + mi * 16;
            float c1a = c1s[rl * 6 + s];
            float c1b = c1s[(rl + 8) * 6 + s];
            float c2a = c2s[rl * 6 + s];
            float c2b = c2s[(rl + 8) * 6 + s];
#pragma unroll
            for (int ni = 0; ni < 4; ni++) {
                Y[mi][ni][0] += c1a * P[mi][ni][0];
                Y[mi][ni][1] += c1a * P[mi][ni][1];
                Y[mi][ni][2] += c1b * P[mi][ni][2];
                Y[mi][ni][3] += c1b * P[mi][ni][3];
                Z[mi][ni][0] += c2a * P[mi][ni][0];
                Z[mi][ni][1] += c2a * P[mi][ni][1];
                Z[mi][ni][2] += c2b * P[mi][ni][2];
                Z[mi][ni][3] += c2b * P[mi][ni][3];
                P[mi][ni][0] = 0.f; P[mi][ni][1] = 0.f;
                P[mi][ni][2] = 0.f; P[mi][ni][3] = 0.f;
            }
        }
    }

    __syncthreads();
    ldW(Bw, g_Wc1h);
    ldW(Wc2s, g_Wc2h);
    asm volatile("cp.async.commit_group;" ::: "memory");

    __half* Yt = Ah;
    __half* Zt = Ah + 64 * STR;
#pragma unroll
    for (int mi = 0; mi < 2; mi++) {
        int row = rowa + mi * 16;
#pragma unroll
        for (int ni = 0; ni < 4; ni++) {
            int col = wn * 32 + ni * 8 + tg * 2;
            *reinterpret_cast<__half2*>(Yt + row * STR + col) =
                __floats2half2_rn(Y[mi][ni][0], Y[mi][ni][1]);
            *reinterpret_cast<__half2*>(Yt + (row + 8) * STR + col) =
                __floats2half2_rn(Y[mi][ni][2], Y[mi][ni][3]);
            *reinterpret_cast<__half2*>(Zt + row * STR + col) =
                __floats2half2_rn(Z[mi][ni][0], Z[mi][ni][1]);
            *reinterpret_cast<__half2*>(Zt + (row + 8) * STR + col) =
                __floats2half2_rn(Z[mi][ni][2], Z[mi][ni][3]);
        }
    }
    asm volatile("cp.async.wait_group 0;" ::: "memory");
    __syncthreads();

    mmastep(Yt, Bw);
    mmastep(Zt, Wc2s);

#pragma unroll
    for (int mi = 0; mi < 2; mi++) {
        int ra = n0 + rowa + mi * 16;
#pragma unroll
        for (int ni = 0; ni < 4; ni++) {
            int col = wn * 32 + ni * 8 + tg * 2;
            float b0 = 6.0f * bc[col];
            float b1 = 6.0f * bc[col + 1];
            if (ra < NN) {
                float2 v = make_float2(P[mi][ni][0] + b0, P[mi][ni][1] + b1);
                *reinterpret_cast<float2*>(&out[(size_t)ra * FF + col]) = v;
            }
            if (ra + 8 < NN) {
                float2 v = make_float2(P[mi][ni][2] + b0, P[mi][ni][3] + b1);
                *reinterpret_cast<float2*>(&out[(size_t)(ra + 8) * FF + col]) = v;
            }
        }
    }
}

// ---------------- launch ----------------
extern "C" void kernel_launch(void* const* d_in, const int* in_sizes, int n_in,
                              void* d_out, int out_size) {
    const float* node_h = (const float*)d_in[0];
    const float* W      = (const float*)d_in[1];
    const float* att1   = (const float*)d_in[2];
    const float* att2   = (const float*)d_in[3];
    const float* Wc     = (const float*)d_in[4];
    const float* bc     = (const float*)d_in[5];
    const int*   esrc   = (const int*)d_in[6];
    const int*   edst   = (const int*)d_in[7];
    const int*   erel   = (const int*)d_in[8];
    float* out = (float*)d_out;

    static int inited = 0;
    static cudaStream_t s1;
    static cudaEvent_t evFork, evPre;
    if (!inited) {
        cudaFuncSetAttribute(gemm_kernel, cudaFuncAttributeMaxDynamicSharedMemorySize, GEMM_SMEM);
        cudaStreamCreateWithFlags(&s1, cudaStreamNonBlocking);
        cudaEventCreateWithFlags(&evFork, cudaEventDisableTiming);
        cudaEventCreateWithFlags(&evPre, cudaEventDisableTiming);
        inited = 1;
    }

    const int nblk1 = (SEG + 511) / 512;   // 586

    // fork: precompute branch on s1 (independent of CSR build)
    cudaEventRecord(evFork, 0);
    cudaStreamWaitEvent(s1, evFork, 0);
    if (out_size >= NN * FF + RR * FF * FF) {
        cudaMemcpyAsync(out + (size_t)NN * FF, W,
                        sizeof(float) * RR * FF * FF, cudaMemcpyDeviceToDevice, s1);
    }
    precompute_kernel<<<RR * FF + FF, 128, 0, s1>>>(W, att1, att2, Wc);
    nodeh_convert_kernel<<<(NN * FF / 8 + 255) / 256, 256, 0, s1>>>(node_h);
    cudaEventRecord(evPre, s1);

    // CSR branch on stream 0 (g_cnt is all-zero: static init / restored by gemm)
    hist_kernel<<<(EE / 8 + 255) / 256, 256>>>((const int4*)edst, (const int4*)erel);
    scan1_kernel<<<nblk1, 512>>>();
    scan2_kernel<<<1, 1024>>>(nblk1);
    permute_kernel<<<(EE / 4 + 255) / 256, 256>>>((const int4*)esrc, (const int4*)edst,
                                                  (const int4*)erel);

    // join precompute before gather
    cudaStreamWaitEvent(0, evPre, 0);

    gather_kernel<<<(SEG + 15) / 16, 256>>>();
    gemm_kernel<<<(NN + 63) / 64, 256, GEMM_SMEM>>>(out, bc);
}